// round 8
// baseline (speedup 1.0000x reference)
#include <cuda_runtime.h>
#include <cuda_bf16.h>
#include <cstdint>
#include <cstddef>
#include <math.h>

#define N_FFT   16000
#define BATCH   512
#define D_IN    2048
#define ODIM    3000
#define OPAD    3072
#define KDIM    16000

// Scratch (device globals — allocation-free per harness rules)
__device__ float2 g_CBUF[BATCH * N_FFT];                  // 64 MB
__device__ float2 g_TW[N_FFT];                            // twiddles
__device__ __align__(16) signed char g_Zhi[BATCH * KDIM]; // 8 MB
__device__ __align__(16) signed char g_Zlo[BATCH * KDIM]; // 8 MB
__device__ __align__(16) signed char g_Whi[OPAD * KDIM];  // 49 MB
__device__ __align__(16) signed char g_Wlo[OPAD * KDIM];  // 49 MB
__device__ float g_Zs[BATCH];
__device__ float g_Ws[OPAD];

static __device__ __forceinline__ float2 cmulf(float2 a, float2 b) {
    return make_float2(a.x * b.x - a.y * b.y, a.x * b.y + a.y * b.x);
}
static __device__ __forceinline__ unsigned smem_u32(const void* p) {
    unsigned a;
    asm("{ .reg .u64 t; cvta.to.shared.u64 t, %1; cvt.u32.u64 %0, t; }" : "=r"(a) : "l"(p));
    return a;
}
static __device__ __forceinline__ unsigned swz128(unsigned off) {
    return off ^ ((off >> 3) & 0x70);
}
#define CP_ASYNC16(dst, src) \
    asm volatile("cp.async.cg.shared.global [%0], [%1], 16;" :: "r"(dst), "l"(src))
#define CP_COMMIT() asm volatile("cp.async.commit_group;" ::: "memory")
#define CP_WAIT1()  asm volatile("cp.async.wait_group 1;" ::: "memory")

static __device__ __forceinline__ void ldsm_x4(unsigned addr, unsigned* r) {
    asm volatile("ldmatrix.sync.aligned.m8n8.x4.shared.b16 {%0,%1,%2,%3}, [%4];"
                 : "=r"(r[0]), "=r"(r[1]), "=r"(r[2]), "=r"(r[3]) : "r"(addr));
}
// s8 IMMA m16n8k32, s32 accumulate
static __device__ __forceinline__ void mma_s8(int* c, const unsigned* a, const unsigned* b) {
    asm volatile(
        "mma.sync.aligned.m16n8k32.row.col.s32.s8.s8.s32 "
        "{%0,%1,%2,%3}, {%4,%5,%6,%7}, {%8,%9}, {%0,%1,%2,%3};"
        : "+r"(c[0]), "+r"(c[1]), "+r"(c[2]), "+r"(c[3])
        : "r"(a[0]), "r"(a[1]), "r"(a[2]), "r"(a[3]), "r"(b[0]), "r"(b[1]));
}
// quantize x*unit into hi/lo int8 limbs (q = 128*hi + lo, |q| <= 16256)
static __device__ __forceinline__ void quant2(float x, float unit, int& hi, int& lo) {
    int q = __float2int_rn(x * unit);
    hi = __float2int_rn((float)q * (1.0f / 128.0f));   // exact /128, rn
    lo = q - (hi << 7);
}

// ---------------------------------------------------------------------------
__global__ void tw_init_kernel() {
    int j = blockIdx.x * blockDim.x + threadIdx.x;
    if (j < N_FFT) {
        double ang = -2.0 * 3.14159265358979323846 * (double)j / (double)N_FFT;
        double s, c;
        sincos(ang, &s, &c);
        g_TW[j] = make_float2((float)c, (float)s);
    }
}

__global__ void zero_cbuf_kernel() {
    int i = blockIdx.x * blockDim.x + threadIdx.x;
    const int n4 = BATCH * N_FFT * 2 / 4;
    if (i < n4) {
        reinterpret_cast<float4*>(g_CBUF)[i] = make_float4(0.f, 0.f, 0.f, 0.f);
    }
}

// ---------------------------------------------------------------------------
// W -> int8 double-limb planes, per-row scale. One CTA (256 thr) per row.
// ---------------------------------------------------------------------------
__global__ __launch_bounds__(256) void wconv_kernel(const float* __restrict__ Wm) {
    __shared__ float red[8];
    const int r = blockIdx.x;
    const int tid = threadIdx.x;
    uchar4* hiRow = reinterpret_cast<uchar4*>(g_Whi + (size_t)r * KDIM);
    uchar4* loRow = reinterpret_cast<uchar4*>(g_Wlo + (size_t)r * KDIM);

    if (r >= ODIM) {
        for (int i = tid; i < KDIM / 4; i += 256) {
            hiRow[i] = make_uchar4(0, 0, 0, 0);
            loRow[i] = make_uchar4(0, 0, 0, 0);
        }
        if (tid == 0) g_Ws[r] = 0.f;
        return;
    }
    const float4* row4 = reinterpret_cast<const float4*>(Wm + (size_t)r * KDIM);
    float m = 0.f;
    for (int i = tid; i < KDIM / 4; i += 256) {
        float4 v = row4[i];
        m = fmaxf(m, fmaxf(fmaxf(fabsf(v.x), fabsf(v.y)), fmaxf(fabsf(v.z), fabsf(v.w))));
    }
#pragma unroll
    for (int o = 16; o > 0; o >>= 1) m = fmaxf(m, __shfl_xor_sync(0xffffffffu, m, o));
    if ((tid & 31) == 0) red[tid >> 5] = m;
    __syncthreads();
    if (tid < 8) {
        float v = red[tid];
#pragma unroll
        for (int o = 4; o > 0; o >>= 1) v = fmaxf(v, __shfl_xor_sync(0xffu, v, o));
        if (tid == 0) red[0] = v;
    }
    __syncthreads();
    const float M = red[0];
    const float unit = (M > 0.f) ? (16256.0f / M) : 0.f;
    for (int i = tid; i < KDIM / 4; i += 256) {
        float4 v = row4[i];
        int h0, l0, h1, l1, h2, l2, h3, l3;
        quant2(v.x, unit, h0, l0);
        quant2(v.y, unit, h1, l1);
        quant2(v.z, unit, h2, l2);
        quant2(v.w, unit, h3, l3);
        hiRow[i] = make_uchar4((unsigned char)(signed char)h0, (unsigned char)(signed char)h1,
                               (unsigned char)(signed char)h2, (unsigned char)(signed char)h3);
        loRow[i] = make_uchar4((unsigned char)(signed char)l0, (unsigned char)(signed char)l1,
                               (unsigned char)(signed char)l2, (unsigned char)(signed char)l3);
    }
    if (tid == 0) g_Ws[r] = M / 16256.0f;
}

// ---------------------------------------------------------------------------
// Count sketch (packed complex c = p1 + i*p2)
// ---------------------------------------------------------------------------
__global__ void sketch_kernel(const float* __restrict__ x0, const float* __restrict__ x1,
                              const float* __restrict__ s1, const float* __restrict__ s2,
                              const int* __restrict__ h1, const int* __restrict__ h2) {
    int idx = blockIdx.x * blockDim.x + threadIdx.x;
    if (idx >= BATCH * D_IN) return;
    int b = idx / D_IN;
    int a = idx - b * D_IN;
    float v1 = s1[a] * x0[idx];
    float v2 = s2[a] * x1[idx];
    float2* row = g_CBUF + (size_t)b * N_FFT;
    atomicAdd(&row[h1[a]].x, v1);
    atomicAdd(&row[h2[a]].y, v2);
}

// ---------------------------------------------------------------------------
// 16000-pt complex FFT, one CTA per batch row, whole row in smem.
// N = 128 * 125.
//  Step A: radix-4 x3 + radix-2 over n1 (chunk q holds k1 = digitrev_{4,4,4,2}(q))
//  Step B: twiddle W_N^{n2*k1}  (folded into Step C stage 0)
//  Step C: radix-5 x3 per chunk (slot j holds k2 = rev5(j))
//  Output phase gathers (digit-reversed source) -> linear global stores.
//  INV epilogue: row max reduce + int8 double-limb quantize into g_Zhi/g_Zlo.
// ---------------------------------------------------------------------------
template <bool INV>
__global__ __launch_bounds__(512) void fft_kernel() {
    extern __shared__ float2 sm[];
    float2* A    = sm;            // 16000
    float2* W125 = sm + N_FFT;    // 125
    __shared__ float sred[16];

    const int b   = blockIdx.x;
    const int tid = threadIdx.x;
    const int T   = blockDim.x;   // 512
    float2* row = g_CBUF + (size_t)b * N_FFT;

    // ---- load phase ----
    if (!INV) {
        for (int k = tid; k < N_FFT; k += T) A[k] = row[k];
    } else {
        for (int k = tid; k < N_FFT; k += T) {
            float2 C = row[k];
            float2 D = row[k == 0 ? 0 : N_FFT - k];
            float2 F1 = make_float2(0.5f * (C.x + D.x), 0.5f * (C.y - D.y));
            float2 F2 = make_float2(0.5f * (C.y + D.y), 0.5f * (D.x - C.x));
            A[k] = cmulf(F1, F2);
        }
    }
    for (int m = tid; m < 125; m += T) {
        float2 t = g_TW[128 * m];        // W_125^m
        if (INV) t.y = -t.y;
        W125[m] = t;
    }
    __syncthreads();

    // ---- Step A: radix-4 x3 stages ----
    {
        const int subs4[3] = {32, 8, 2};
        const int twm[3]   = {125, 500, 2000};
#pragma unroll
        for (int s = 0; s < 3; ++s) {
            const int sub = subs4[s];
            const int L = 4 * sub;
            const int tm = twm[s];
            for (int i = tid; i < 4000; i += T) {
                int n2 = i % 125;
                int t  = i / 125;               // 0..31
                int blk = t / sub;
                int j   = t - blk * sub;
                int base = (blk * L + j) * 125 + n2;
                const int st = sub * 125;
                float2 x0 = A[base];
                float2 x1 = A[base + st];
                float2 x2 = A[base + 2 * st];
                float2 x3 = A[base + 3 * st];
                float2 t0 = make_float2(x0.x + x2.x, x0.y + x2.y);
                float2 t1 = make_float2(x0.x - x2.x, x0.y - x2.y);
                float2 t2 = make_float2(x1.x + x3.x, x1.y + x3.y);
                float2 t3 = make_float2(x1.x - x3.x, x1.y - x3.y);
                // fwd: -i*t3 ; inv: +i*t3
                float2 it3 = INV ? make_float2(-t3.y, t3.x) : make_float2(t3.y, -t3.x);
                float2 y0 = make_float2(t0.x + t2.x, t0.y + t2.y);
                float2 y2 = make_float2(t0.x - t2.x, t0.y - t2.y);
                float2 y1 = make_float2(t1.x + it3.x, t1.y + it3.y);
                float2 y3 = make_float2(t1.x - it3.x, t1.y - it3.y);
                float2 w1 = g_TW[j * tm];
                float2 w2 = g_TW[2 * j * tm];
                float2 w3 = g_TW[3 * j * tm];
                if (INV) { w1.y = -w1.y; w2.y = -w2.y; w3.y = -w3.y; }
                A[base]          = y0;
                A[base + st]     = cmulf(y1, w1);
                A[base + 2 * st] = cmulf(y2, w2);
                A[base + 3 * st] = cmulf(y3, w3);
            }
            __syncthreads();
        }
        // final radix-2 stage (adjacent slots, no twiddle)
        for (int i = tid; i < 8000; i += T) {
            int n2 = i % 125;
            int m  = i / 125;                  // 0..63
            int p  = (2 * m) * 125 + n2;
            int p2 = p + 125;
            float2 u = A[p], v = A[p2];
            A[p]  = make_float2(u.x + v.x, u.y + v.y);
            A[p2] = make_float2(u.x - v.x, u.y - v.y);
        }
        __syncthreads();
    }

    // ---- Step C: 3 radix-5 DIF stages; stage 0 folds Step-B twiddle ----
    {
        const float c1 = 0.309016994374947424f;
        const float c2 = -0.809016994374947424f;
        const float S1 = INV ? -0.951056516295153572f : 0.951056516295153572f;
        const float S2 = INV ? -0.587785252292473129f : 0.587785252292473129f;
        const int Ls[3]   = {125, 25, 5};
        const int subs[3] = {25, 5, 1};
        const int fs[3]   = {1, 5, 25};
#pragma unroll
        for (int s = 0; s < 3; ++s) {
            const int L = Ls[s], sub = subs[s], f = fs[s];
            for (int i = tid; i < 3200; i += T) {
                int q = i / 25;
                int t = i - q * 25;
                int blk = t / sub;
                int j   = t - blk * sub;
                int base = q * 125 + blk * L + j;
                float2 x0 = A[base];
                float2 x1 = A[base + sub];
                float2 x2 = A[base + 2 * sub];
                float2 x3 = A[base + 3 * sub];
                float2 x4 = A[base + 4 * sub];
                if (s == 0) {
                    // folded Step B: element n2 = j + 25*i_sub, k1 = digitrev(q)
                    int k1 = (q >> 5) + ((q >> 3) & 3) * 4 + ((q >> 1) & 3) * 16 + (q & 1) * 64;
                    float2 b0 = g_TW[j * k1];
                    float2 b1 = g_TW[(j + 25) * k1];
                    float2 b2 = g_TW[(j + 50) * k1];
                    float2 b3 = g_TW[(j + 75) * k1];
                    float2 b4 = g_TW[(j + 100) * k1];
                    if (INV) { b0.y = -b0.y; b1.y = -b1.y; b2.y = -b2.y; b3.y = -b3.y; b4.y = -b4.y; }
                    x0 = cmulf(x0, b0);
                    x1 = cmulf(x1, b1);
                    x2 = cmulf(x2, b2);
                    x3 = cmulf(x3, b3);
                    x4 = cmulf(x4, b4);
                }
                float t1x = x1.x + x4.x, t1y = x1.y + x4.y;
                float t2x = x2.x + x3.x, t2y = x2.y + x3.y;
                float t3x = x1.x - x4.x, t3y = x1.y - x4.y;
                float t4x = x2.x - x3.x, t4y = x2.y - x3.y;
                float2 y0 = make_float2(x0.x + t1x + t2x, x0.y + t1y + t2y);
                float ax = x0.x + c1 * t1x + c2 * t2x;
                float ay = x0.y + c1 * t1y + c2 * t2y;
                float bx = S1 * t3x + S2 * t4x;
                float by = S1 * t3y + S2 * t4y;
                float dx = x0.x + c2 * t1x + c1 * t2x;
                float dy = x0.y + c2 * t1y + c1 * t2y;
                float ex = S2 * t3x - S1 * t4x;
                float ey = S2 * t3y - S1 * t4y;
                float2 y1 = make_float2(ax + by, ay - bx);
                float2 y4 = make_float2(ax - by, ay + bx);
                float2 y2 = make_float2(dx + ey, dy - ex);
                float2 y3 = make_float2(dx - ey, dy + ex);
                int jf = j * f;
                A[base]           = y0;
                A[base + sub]     = cmulf(y1, W125[jf]);
                A[base + 2 * sub] = cmulf(y2, W125[2 * jf]);
                A[base + 3 * sub] = cmulf(y3, W125[3 * jf]);
                A[base + 4 * sub] = cmulf(y4, W125[4 * jf]);
            }
            __syncthreads();
        }
    }

    // ---- INV: row max over real parts (for int8 quantization) ----
    float unit = 0.f;
    if (INV) {
        float m = 0.f;
        for (int i = tid; i < N_FFT; i += T) m = fmaxf(m, fabsf(A[i].x));
#pragma unroll
        for (int o = 16; o > 0; o >>= 1) m = fmaxf(m, __shfl_xor_sync(0xffffffffu, m, o));
        if ((tid & 31) == 0) sred[tid >> 5] = m;
        __syncthreads();
        if (tid < 16) {
            float v = sred[tid];
#pragma unroll
            for (int o = 8; o > 0; o >>= 1) v = fmaxf(v, __shfl_xor_sync(0xffffu, v, o));
            if (tid == 0) sred[0] = v;
        }
        __syncthreads();
        const float M = sred[0];
        unit = (M > 0.f) ? (16256.0f / M) : 0.f;
        if (tid == 0) g_Zs[b] = M * (1.0f / (float)N_FFT) / 16256.0f;
    }

    // ---- output: gather from digit-reversed source, store linearly ----
    for (int k = tid; k < N_FFT; k += T) {
        int k1 = k & 127;
        int k2 = k >> 7;
        int q = (k1 & 3) * 32 + ((k1 >> 2) & 3) * 8 + ((k1 >> 4) & 3) * 2 + (k1 >> 6);
        int j = (k2 % 5) * 25 + ((k2 / 5) % 5) * 5 + (k2 / 25);
        float2 v = A[q * 125 + j];
        if (!INV) {
            row[k] = v;
        } else {
            int hi, lo;
            quant2(v.x, unit, hi, lo);
            g_Zhi[(size_t)b * KDIM + k] = (signed char)hi;
            g_Zlo[(size_t)b * KDIM + k] = (signed char)lo;
        }
    }
}

// ---------------------------------------------------------------------------
// int8 double-limb IMMA GEMM:
//   out = relu(s_z[m]*s_w[n]*(16384*HH + 128*X) + b), X = HL + LH, LL dropped.
// Tile 128x96, k-chunk 128 int8, grid (32,4)=128 CTAs, 256 thr, 3-stage cp.async.
// Stage: Ahi 16K | Alo 16K | Bhi 12K | Blo 12K = 56 KB; x3 = 168 KB.
// ---------------------------------------------------------------------------
#define GTK 128
#define GITERS (KDIM / GTK)          // 125
#define A_PL 16384
#define B_PL 12288
#define STG_BYTES (2 * A_PL + 2 * B_PL)   // 57344
#define GEMM_SMEM (3 * STG_BYTES)         // 172032

static __device__ __forceinline__ void gemm_issue_stage(unsigned sb, int tid, int k0,
                                                        int m0, int n0g) {
    const char* zhi = reinterpret_cast<const char*>(g_Zhi);
    const char* zlo = reinterpret_cast<const char*>(g_Zlo);
    const char* whi = reinterpret_cast<const char*>(g_Whi);
    const char* wlo = reinterpret_cast<const char*>(g_Wlo);
#pragma unroll
    for (int i = 0; i < 4; ++i) {                 // A: 128 rows x 8 segs
        int lin = i * 256 + tid;
        int r = lin >> 3, seg = lin & 7;
        unsigned d = sb + swz128((unsigned)(r * 128 + seg * 16));
        size_t so = (size_t)(m0 + r) * KDIM + k0 + seg * 16;
        CP_ASYNC16(d, zhi + so);
        CP_ASYNC16(d + A_PL, zlo + so);
    }
#pragma unroll
    for (int i = 0; i < 3; ++i) {                 // B: 96 rows x 8 segs
        int lin = i * 256 + tid;
        int r = lin >> 3, seg = lin & 7;
        unsigned d = sb + 2 * A_PL + swz128((unsigned)(r * 128 + seg * 16));
        size_t so = (size_t)(n0g + r) * KDIM + k0 + seg * 16;
        CP_ASYNC16(d, whi + so);
        CP_ASYNC16(d + B_PL, wlo + so);
    }
}

__global__ __launch_bounds__(256, 1) void gemm_imma_kernel(const float* __restrict__ bias,
                                                           float* __restrict__ out) {
    extern __shared__ char gsm[];
    const unsigned sbase = smem_u32(gsm);
    const int tid  = threadIdx.x;
    const int lane = tid & 31;
    const int wid  = tid >> 5;
    const int wm   = wid >> 1;          // 0..3 -> 32 m rows each
    const int wn   = wid & 1;           // 0..1 -> 48 n cols each
    const int n0 = blockIdx.x * 96;
    const int m0 = blockIdx.y * 128;

    int accH[2][6][4];                  // hi*hi
    int accX[2][6][4];                  // hi*lo + lo*hi
#pragma unroll
    for (int i = 0; i < 2; ++i)
#pragma unroll
        for (int j = 0; j < 6; ++j)
#pragma unroll
            for (int e = 0; e < 4; ++e) { accH[i][j][e] = 0; accX[i][j][e] = 0; }

    gemm_issue_stage(sbase, tid, 0, m0, n0);
    CP_COMMIT();
    gemm_issue_stage(sbase + STG_BYTES, tid, GTK, m0, n0);
    CP_COMMIT();

    const unsigned aRowSel = (unsigned)(lane & 15) * 128 + ((unsigned)(lane >> 4) << 4);
    const unsigned bRowSel = (unsigned)((lane & 7) | (((lane >> 4) & 1) << 3)) * 128 +
                             (((unsigned)(lane >> 3) & 1) << 4);

    for (int c = 0; c < GITERS; ++c) {
        CP_WAIT1();
        __syncthreads();
        if (c + 2 < GITERS) {
            gemm_issue_stage(sbase + ((c + 2) % 3) * STG_BYTES, tid, (c + 2) * GTK, m0, n0);
        }
        CP_COMMIT();

        const unsigned Ab = sbase + (c % 3) * STG_BYTES;
        const unsigned Bb = Ab + 2 * A_PL;
#pragma unroll
        for (int ks = 0; ks < 4; ++ks) {          // 4 sub-chunks of k=32
            unsigned Af[2][2][4];
            unsigned Bf[2][3][4];
#pragma unroll
            for (int p = 0; p < 2; ++p) {
#pragma unroll
                for (int mf = 0; mf < 2; ++mf) {
                    unsigned off = (unsigned)((wm * 32 + mf * 16) * 128 + ks * 32) + aRowSel;
                    ldsm_x4(Ab + p * A_PL + swz128(off), Af[p][mf]);
                }
#pragma unroll
                for (int g = 0; g < 3; ++g) {
                    unsigned off = (unsigned)((wn * 48 + g * 16) * 128 + ks * 32) + bRowSel;
                    ldsm_x4(Bb + p * B_PL + swz128(off), Bf[p][g]);
                }
            }
#pragma unroll
            for (int mf = 0; mf < 2; ++mf)
#pragma unroll
                for (int nf = 0; nf < 6; ++nf) {
                    const unsigned* bHi = &Bf[0][nf >> 1][(nf & 1) * 2];
                    const unsigned* bLo = &Bf[1][nf >> 1][(nf & 1) * 2];
                    mma_s8(accH[mf][nf], Af[0][mf], bHi);   // hi*hi
                    mma_s8(accX[mf][nf], Af[0][mf], bLo);   // hi*lo
                    mma_s8(accX[mf][nf], Af[1][mf], bHi);   // lo*hi
                }
        }
        __syncthreads();
    }

    // ---- epilogue: combine limbs, scale, bias + relu ----
#pragma unroll
    for (int mf = 0; mf < 2; ++mf) {
        int mlo = m0 + wm * 32 + mf * 16 + (lane >> 2);
        float szA = g_Zs[mlo];
        float szB = g_Zs[mlo + 8];
#pragma unroll
        for (int nf = 0; nf < 6; ++nf) {
            int n = n0 + wn * 48 + nf * 8 + 2 * (lane & 3);
            if (n < ODIM) {
                float sw0 = g_Ws[n], sw1 = g_Ws[n + 1];
                float b0 = bias[n], b1 = bias[n + 1];
                float r0 = 16384.f * (float)accH[mf][nf][0] + 128.f * (float)accX[mf][nf][0];
                float r1 = 16384.f * (float)accH[mf][nf][1] + 128.f * (float)accX[mf][nf][1];
                float r2 = 16384.f * (float)accH[mf][nf][2] + 128.f * (float)accX[mf][nf][2];
                float r3 = 16384.f * (float)accH[mf][nf][3] + 128.f * (float)accX[mf][nf][3];
                float2 v0, v1;
                v0.x = fmaxf(fmaf(r0, szA * sw0, b0), 0.f);
                v0.y = fmaxf(fmaf(r1, szA * sw1, b1), 0.f);
                v1.x = fmaxf(fmaf(r2, szB * sw0, b0), 0.f);
                v1.y = fmaxf(fmaf(r3, szB * sw1, b1), 0.f);
                *reinterpret_cast<float2*>(out + (size_t)mlo * ODIM + n) = v0;
                *reinterpret_cast<float2*>(out + (size_t)(mlo + 8) * ODIM + n) = v1;
            }
        }
    }
}

// ---------------------------------------------------------------------------
extern "C" void kernel_launch(void* const* d_in, const int* in_sizes, int n_in,
                              void* d_out, int out_size) {
    const float* x0  = (const float*)d_in[0];
    const float* x1  = (const float*)d_in[1];
    const float* s1  = (const float*)d_in[2];
    const float* s2  = (const float*)d_in[3];
    const float* Wm  = (const float*)d_in[4];
    const float* bia = (const float*)d_in[5];
    const int*   h1  = (const int*)d_in[6];
    const int*   h2  = (const int*)d_in[7];
    float* out = (float*)d_out;

    const int FFT_SMEM = (N_FFT + 128) * (int)sizeof(float2);  // 129 KB

    cudaFuncSetAttribute(fft_kernel<false>, cudaFuncAttributeMaxDynamicSharedMemorySize, FFT_SMEM);
    cudaFuncSetAttribute(fft_kernel<true>,  cudaFuncAttributeMaxDynamicSharedMemorySize, FFT_SMEM);
    cudaFuncSetAttribute(gemm_imma_kernel, cudaFuncAttributeMaxDynamicSharedMemorySize, GEMM_SMEM);

    tw_init_kernel<<<(N_FFT + 255) / 256, 256>>>();

    const int n4 = BATCH * N_FFT * 2 / 4;
    zero_cbuf_kernel<<<(n4 + 255) / 256, 256>>>();

    sketch_kernel<<<(BATCH * D_IN + 255) / 256, 256>>>(x0, x1, s1, s2, h1, h2);

    wconv_kernel<<<OPAD, 256>>>(Wm);

    fft_kernel<false><<<BATCH, 512, FFT_SMEM>>>();
    fft_kernel<true><<<BATCH, 512, FFT_SMEM>>>();

    gemm_imma_kernel<<<dim3((ODIM + 95) / 96, BATCH / 128), 256, GEMM_SMEM>>>(bia, out);
}

// round 9
// speedup vs baseline: 2.3335x; 2.3335x over previous
#include <cuda_runtime.h>
#include <cuda_fp16.h>
#include <cstdint>
#include <cstddef>
#include <math.h>

#define N_FFT   16000
#define BATCH   512
#define D_IN    2048
#define ODIM    3000
#define OPAD    3072
#define KDIM    16000

// Scratch (device globals — allocation-free per harness rules)
__device__ float2 g_CBUF[BATCH * N_FFT];               // 64 MB
__device__ float2 g_TW[N_FFT];                         // twiddles
__device__ __align__(16) __half g_Zh[BATCH * KDIM];    // 16 MB (single limb, normalized)
__device__ __align__(16) __half g_Whi[OPAD * KDIM];    // 96 MB
__device__ __align__(16) __half g_Wlo[OPAD * KDIM];    // 96 MB
__device__ float g_Zs[BATCH];                          // per-row z scale
__device__ float g_Ws[OPAD];                           // per-row w scale

static __device__ __forceinline__ float2 cmulf(float2 a, float2 b) {
    return make_float2(a.x * b.x - a.y * b.y, a.x * b.y + a.y * b.x);
}
static __device__ __forceinline__ unsigned smem_u32(const void* p) {
    unsigned a;
    asm("{ .reg .u64 t; cvta.to.shared.u64 t, %1; cvt.u32.u64 %0, t; }" : "=r"(a) : "l"(p));
    return a;
}
static __device__ __forceinline__ unsigned swz128(unsigned off) {
    return off ^ ((off >> 3) & 0x70);
}
#define CP_ASYNC16(dst, src) \
    asm volatile("cp.async.cg.shared.global [%0], [%1], 16;" :: "r"(dst), "l"(src))
#define CP_COMMIT() asm volatile("cp.async.commit_group;" ::: "memory")
#define CP_WAIT1()  asm volatile("cp.async.wait_group 1;" ::: "memory")

static __device__ __forceinline__ void ldsm_x4(unsigned addr, unsigned* r) {
    asm volatile("ldmatrix.sync.aligned.m8n8.x4.shared.b16 {%0,%1,%2,%3}, [%4];"
                 : "=r"(r[0]), "=r"(r[1]), "=r"(r[2]), "=r"(r[3]) : "r"(addr));
}
// fp16 HMMA m16n8k16, f32 accumulate
static __device__ __forceinline__ void mma_f16(float* c, const unsigned* a, const unsigned* b) {
    asm volatile(
        "mma.sync.aligned.m16n8k16.row.col.f32.f16.f16.f32 "
        "{%0,%1,%2,%3}, {%4,%5,%6,%7}, {%8,%9}, {%0,%1,%2,%3};"
        : "+f"(c[0]), "+f"(c[1]), "+f"(c[2]), "+f"(c[3])
        : "r"(a[0]), "r"(a[1]), "r"(a[2]), "r"(a[3]), "r"(b[0]), "r"(b[1]));
}

// ---------------------------------------------------------------------------
__global__ void tw_init_kernel() {
    int j = blockIdx.x * blockDim.x + threadIdx.x;
    if (j < N_FFT) {
        double ang = -2.0 * 3.14159265358979323846 * (double)j / (double)N_FFT;
        double s, c;
        sincos(ang, &s, &c);
        g_TW[j] = make_float2((float)c, (float)s);
    }
}

__global__ void zero_cbuf_kernel() {
    int i = blockIdx.x * blockDim.x + threadIdx.x;
    const int n4 = BATCH * N_FFT * 2 / 4;
    if (i < n4) {
        reinterpret_cast<float4*>(g_CBUF)[i] = make_float4(0.f, 0.f, 0.f, 0.f);
    }
}

// ---------------------------------------------------------------------------
// W -> fp16 hi/lo planes, per-row normalized. One CTA (256 thr) per row.
// ---------------------------------------------------------------------------
__global__ __launch_bounds__(256) void wconv_kernel(const float* __restrict__ Wm) {
    __shared__ float red[8];
    const int r = blockIdx.x;
    const int tid = threadIdx.x;
    uint2* hiRow = reinterpret_cast<uint2*>(g_Whi + (size_t)r * KDIM);
    uint2* loRow = reinterpret_cast<uint2*>(g_Wlo + (size_t)r * KDIM);

    if (r >= ODIM) {
        for (int i = tid; i < KDIM / 4; i += 256) {
            hiRow[i] = make_uint2(0u, 0u);
            loRow[i] = make_uint2(0u, 0u);
        }
        if (tid == 0) g_Ws[r] = 0.f;
        return;
    }
    const float4* row4 = reinterpret_cast<const float4*>(Wm + (size_t)r * KDIM);
    float m = 0.f;
    for (int i = tid; i < KDIM / 4; i += 256) {
        float4 v = row4[i];
        m = fmaxf(m, fmaxf(fmaxf(fabsf(v.x), fabsf(v.y)), fmaxf(fabsf(v.z), fabsf(v.w))));
    }
#pragma unroll
    for (int o = 16; o > 0; o >>= 1) m = fmaxf(m, __shfl_xor_sync(0xffffffffu, m, o));
    if ((tid & 31) == 0) red[tid >> 5] = m;
    __syncthreads();
    if (tid < 8) {
        float v = red[tid];
#pragma unroll
        for (int o = 4; o > 0; o >>= 1) v = fmaxf(v, __shfl_xor_sync(0xffu, v, o));
        if (tid == 0) red[0] = v;
    }
    __syncthreads();
    const float M = red[0];
    const float unit = (M > 0.f) ? (1.0f / M) : 0.f;
    for (int i = tid; i < KDIM / 4; i += 256) {
        float4 v = row4[i];
        float n0 = v.x * unit, n1 = v.y * unit, n2 = v.z * unit, n3 = v.w * unit;
        __half h0 = __float2half_rn(n0), h1 = __float2half_rn(n1);
        __half h2 = __float2half_rn(n2), h3 = __float2half_rn(n3);
        __half l0 = __float2half_rn(n0 - __half2float(h0));
        __half l1 = __float2half_rn(n1 - __half2float(h1));
        __half l2 = __float2half_rn(n2 - __half2float(h2));
        __half l3 = __float2half_rn(n3 - __half2float(h3));
        unsigned hA = ((unsigned)__half_as_ushort(h1) << 16) | __half_as_ushort(h0);
        unsigned hB = ((unsigned)__half_as_ushort(h3) << 16) | __half_as_ushort(h2);
        unsigned lA = ((unsigned)__half_as_ushort(l1) << 16) | __half_as_ushort(l0);
        unsigned lB = ((unsigned)__half_as_ushort(l3) << 16) | __half_as_ushort(l2);
        hiRow[i] = make_uint2(hA, hB);
        loRow[i] = make_uint2(lA, lB);
    }
    if (tid == 0) g_Ws[r] = M;
}

// ---------------------------------------------------------------------------
// Count sketch (packed complex c = p1 + i*p2)
// ---------------------------------------------------------------------------
__global__ void sketch_kernel(const float* __restrict__ x0, const float* __restrict__ x1,
                              const float* __restrict__ s1, const float* __restrict__ s2,
                              const int* __restrict__ h1, const int* __restrict__ h2) {
    int idx = blockIdx.x * blockDim.x + threadIdx.x;
    if (idx >= BATCH * D_IN) return;
    int b = idx / D_IN;
    int a = idx - b * D_IN;
    float v1 = s1[a] * x0[idx];
    float v2 = s2[a] * x1[idx];
    float2* row = g_CBUF + (size_t)b * N_FFT;
    atomicAdd(&row[h1[a]].x, v1);
    atomicAdd(&row[h2[a]].y, v2);
}

// ---------------------------------------------------------------------------
// 16000-pt complex FFT, one CTA per batch row, whole row in smem.
// N = 128 * 125.
//  Step A: radix-4 x3 + radix-2 over n1 (chunk q holds k1 = digitrev(q))
//  Step B: twiddle (folded into Step C stage 0)
//  Step C: radix-5 x3 per chunk (slot j holds k2 = rev5(j))
//  Output gathers (digit-reversed source) -> linear global stores.
//  INV epilogue: row max reduce + fp16 normalized quantize into g_Zh.
// ---------------------------------------------------------------------------
template <bool INV>
__global__ __launch_bounds__(512) void fft_kernel() {
    extern __shared__ float2 sm[];
    float2* A    = sm;            // 16000
    float2* W125 = sm + N_FFT;    // 125
    __shared__ float sred[16];

    const int b   = blockIdx.x;
    const int tid = threadIdx.x;
    const int T   = blockDim.x;   // 512
    float2* row = g_CBUF + (size_t)b * N_FFT;

    // ---- load phase ----
    if (!INV) {
        for (int k = tid; k < N_FFT; k += T) A[k] = row[k];
    } else {
        for (int k = tid; k < N_FFT; k += T) {
            float2 C = row[k];
            float2 D = row[k == 0 ? 0 : N_FFT - k];
            float2 F1 = make_float2(0.5f * (C.x + D.x), 0.5f * (C.y - D.y));
            float2 F2 = make_float2(0.5f * (C.y + D.y), 0.5f * (D.x - C.x));
            A[k] = cmulf(F1, F2);
        }
    }
    for (int m = tid; m < 125; m += T) {
        float2 t = g_TW[128 * m];        // W_125^m
        if (INV) t.y = -t.y;
        W125[m] = t;
    }
    __syncthreads();

    // ---- Step A: radix-4 x3 stages ----
    {
        const int subs4[3] = {32, 8, 2};
        const int twm[3]   = {125, 500, 2000};
#pragma unroll
        for (int s = 0; s < 3; ++s) {
            const int sub = subs4[s];
            const int L = 4 * sub;
            const int tm = twm[s];
            for (int i = tid; i < 4000; i += T) {
                int n2 = i % 125;
                int t  = i / 125;               // 0..31
                int blk = t / sub;
                int j   = t - blk * sub;
                int base = (blk * L + j) * 125 + n2;
                const int st = sub * 125;
                float2 x0 = A[base];
                float2 x1 = A[base + st];
                float2 x2 = A[base + 2 * st];
                float2 x3 = A[base + 3 * st];
                float2 t0 = make_float2(x0.x + x2.x, x0.y + x2.y);
                float2 t1 = make_float2(x0.x - x2.x, x0.y - x2.y);
                float2 t2 = make_float2(x1.x + x3.x, x1.y + x3.y);
                float2 t3 = make_float2(x1.x - x3.x, x1.y - x3.y);
                float2 it3 = INV ? make_float2(-t3.y, t3.x) : make_float2(t3.y, -t3.x);
                float2 y0 = make_float2(t0.x + t2.x, t0.y + t2.y);
                float2 y2 = make_float2(t0.x - t2.x, t0.y - t2.y);
                float2 y1 = make_float2(t1.x + it3.x, t1.y + it3.y);
                float2 y3 = make_float2(t1.x - it3.x, t1.y - it3.y);
                float2 w1 = g_TW[j * tm];
                float2 w2 = g_TW[2 * j * tm];
                float2 w3 = g_TW[3 * j * tm];
                if (INV) { w1.y = -w1.y; w2.y = -w2.y; w3.y = -w3.y; }
                A[base]          = y0;
                A[base + st]     = cmulf(y1, w1);
                A[base + 2 * st] = cmulf(y2, w2);
                A[base + 3 * st] = cmulf(y3, w3);
            }
            __syncthreads();
        }
        // final radix-2 stage (adjacent slots, no twiddle)
        for (int i = tid; i < 8000; i += T) {
            int n2 = i % 125;
            int m  = i / 125;                  // 0..63
            int p  = (2 * m) * 125 + n2;
            int p2 = p + 125;
            float2 u = A[p], v = A[p2];
            A[p]  = make_float2(u.x + v.x, u.y + v.y);
            A[p2] = make_float2(u.x - v.x, u.y - v.y);
        }
        __syncthreads();
    }

    // ---- Step C: 3 radix-5 DIF stages; stage 0 folds Step-B twiddle ----
    {
        const float c1 = 0.309016994374947424f;
        const float c2 = -0.809016994374947424f;
        const float S1 = INV ? -0.951056516295153572f : 0.951056516295153572f;
        const float S2 = INV ? -0.587785252292473129f : 0.587785252292473129f;
        const int Ls[3]   = {125, 25, 5};
        const int subs[3] = {25, 5, 1};
        const int fs[3]   = {1, 5, 25};
#pragma unroll
        for (int s = 0; s < 3; ++s) {
            const int L = Ls[s], sub = subs[s], f = fs[s];
            for (int i = tid; i < 3200; i += T) {
                int q = i / 25;
                int t = i - q * 25;
                int blk = t / sub;
                int j   = t - blk * sub;
                int base = q * 125 + blk * L + j;
                float2 x0 = A[base];
                float2 x1 = A[base + sub];
                float2 x2 = A[base + 2 * sub];
                float2 x3 = A[base + 3 * sub];
                float2 x4 = A[base + 4 * sub];
                if (s == 0) {
                    int k1 = (q >> 5) + ((q >> 3) & 3) * 4 + ((q >> 1) & 3) * 16 + (q & 1) * 64;
                    float2 b0 = g_TW[j * k1];
                    float2 b1 = g_TW[(j + 25) * k1];
                    float2 b2 = g_TW[(j + 50) * k1];
                    float2 b3 = g_TW[(j + 75) * k1];
                    float2 b4 = g_TW[(j + 100) * k1];
                    if (INV) { b0.y = -b0.y; b1.y = -b1.y; b2.y = -b2.y; b3.y = -b3.y; b4.y = -b4.y; }
                    x0 = cmulf(x0, b0);
                    x1 = cmulf(x1, b1);
                    x2 = cmulf(x2, b2);
                    x3 = cmulf(x3, b3);
                    x4 = cmulf(x4, b4);
                }
                float t1x = x1.x + x4.x, t1y = x1.y + x4.y;
                float t2x = x2.x + x3.x, t2y = x2.y + x3.y;
                float t3x = x1.x - x4.x, t3y = x1.y - x4.y;
                float t4x = x2.x - x3.x, t4y = x2.y - x3.y;
                float2 y0 = make_float2(x0.x + t1x + t2x, x0.y + t1y + t2y);
                float ax = x0.x + c1 * t1x + c2 * t2x;
                float ay = x0.y + c1 * t1y + c2 * t2y;
                float bx = S1 * t3x + S2 * t4x;
                float by = S1 * t3y + S2 * t4y;
                float dx = x0.x + c2 * t1x + c1 * t2x;
                float dy = x0.y + c2 * t1y + c1 * t2y;
                float ex = S2 * t3x - S1 * t4x;
                float ey = S2 * t3y - S1 * t4y;
                float2 y1 = make_float2(ax + by, ay - bx);
                float2 y4 = make_float2(ax - by, ay + bx);
                float2 y2 = make_float2(dx + ey, dy - ex);
                float2 y3 = make_float2(dx - ey, dy + ex);
                int jf = j * f;
                A[base]           = y0;
                A[base + sub]     = cmulf(y1, W125[jf]);
                A[base + 2 * sub] = cmulf(y2, W125[2 * jf]);
                A[base + 3 * sub] = cmulf(y3, W125[3 * jf]);
                A[base + 4 * sub] = cmulf(y4, W125[4 * jf]);
            }
            __syncthreads();
        }
    }

    // ---- INV: row max over real parts (for fp16 normalization) ----
    float unit = 0.f;
    if (INV) {
        float m = 0.f;
        for (int i = tid; i < N_FFT; i += T) m = fmaxf(m, fabsf(A[i].x));
#pragma unroll
        for (int o = 16; o > 0; o >>= 1) m = fmaxf(m, __shfl_xor_sync(0xffffffffu, m, o));
        if ((tid & 31) == 0) sred[tid >> 5] = m;
        __syncthreads();
        if (tid < 16) {
            float v = sred[tid];
#pragma unroll
            for (int o = 8; o > 0; o >>= 1) v = fmaxf(v, __shfl_xor_sync(0xffffu, v, o));
            if (tid == 0) sred[0] = v;
        }
        __syncthreads();
        const float M = sred[0];
        unit = (M > 0.f) ? (1.0f / M) : 0.f;
        if (tid == 0) g_Zs[b] = M * (1.0f / (float)N_FFT);
    }

    // ---- output: gather from digit-reversed source, store linearly ----
    for (int k = tid; k < N_FFT; k += T) {
        int k1 = k & 127;
        int k2 = k >> 7;
        int q = (k1 & 3) * 32 + ((k1 >> 2) & 3) * 8 + ((k1 >> 4) & 3) * 2 + (k1 >> 6);
        int j = (k2 % 5) * 25 + ((k2 / 5) % 5) * 5 + (k2 / 25);
        float2 v = A[q * 125 + j];
        if (!INV) {
            row[k] = v;
        } else {
            g_Zh[(size_t)b * KDIM + k] = __float2half_rn(v.x * unit);
        }
    }
}

// ---------------------------------------------------------------------------
// fp16 2-term HMMA GEMM:
//   out = relu(s_z[m]*s_w[n]*(zh·whi + zh·wlo) + b)   (dropped: zlo*w ~2^-11)
// Tile 128x96, k-chunk 64, grid (32,4)=128 CTAs, 256 thr, 3-stage cp.async.
// Stage: A 16K | Bhi 12K | Blo 12K = 40 KB; x3 = 120 KB.
// ---------------------------------------------------------------------------
#define GTK 64
#define GITERS (KDIM / GTK)          // 250
#define A_PL 16384
#define B_PL 12288
#define STG_BYTES (A_PL + 2 * B_PL)  // 40960
#define GEMM_SMEM (3 * STG_BYTES)    // 122880

static __device__ __forceinline__ void gemm_issue_stage(unsigned sb, int tid, int k0,
                                                        int m0, int n0g) {
    const char* zh  = reinterpret_cast<const char*>(g_Zh);
    const char* whi = reinterpret_cast<const char*>(g_Whi);
    const char* wlo = reinterpret_cast<const char*>(g_Wlo);
#pragma unroll
    for (int i = 0; i < 4; ++i) {                 // A: 128 rows x 8 segs
        int lin = i * 256 + tid;
        int r = lin >> 3, seg = lin & 7;
        unsigned d = sb + swz128((unsigned)(r * 128 + seg * 16));
        size_t so = ((size_t)(m0 + r) * KDIM + k0 + seg * 8) * 2;
        CP_ASYNC16(d, zh + so);
    }
#pragma unroll
    for (int i = 0; i < 3; ++i) {                 // B: 96 rows x 8 segs x 2 planes
        int lin = i * 256 + tid;
        int r = lin >> 3, seg = lin & 7;
        unsigned d = sb + A_PL + swz128((unsigned)(r * 128 + seg * 16));
        size_t so = ((size_t)(n0g + r) * KDIM + k0 + seg * 8) * 2;
        CP_ASYNC16(d, whi + so);
        CP_ASYNC16(d + B_PL, wlo + so);
    }
}

__global__ __launch_bounds__(256, 1) void gemm_hmma_kernel(const float* __restrict__ bias,
                                                           float* __restrict__ out) {
    extern __shared__ char gsm[];
    const unsigned sbase = smem_u32(gsm);
    const int tid  = threadIdx.x;
    const int lane = tid & 31;
    const int wid  = tid >> 5;
    const int wm   = wid >> 1;          // 0..3 -> 32 m rows each
    const int wn   = wid & 1;           // 0..1 -> 48 n cols each
    const int n0 = blockIdx.x * 96;
    const int m0 = blockIdx.y * 128;

    float acc[2][6][4];
#pragma unroll
    for (int i = 0; i < 2; ++i)
#pragma unroll
        for (int j = 0; j < 6; ++j)
#pragma unroll
            for (int e = 0; e < 4; ++e) acc[i][j][e] = 0.f;

    gemm_issue_stage(sbase, tid, 0, m0, n0);
    CP_COMMIT();
    gemm_issue_stage(sbase + STG_BYTES, tid, GTK, m0, n0);
    CP_COMMIT();

    const unsigned aRowSel = (unsigned)(lane & 15) * 128 + ((unsigned)(lane >> 4) << 4);
    const unsigned bRowSel = (unsigned)((lane & 7) | (((lane >> 4) & 1) << 3)) * 128 +
                             (((unsigned)(lane >> 3) & 1) << 4);

    for (int c = 0; c < GITERS; ++c) {
        CP_WAIT1();
        __syncthreads();
        if (c + 2 < GITERS) {
            gemm_issue_stage(sbase + ((c + 2) % 3) * STG_BYTES, tid, (c + 2) * GTK, m0, n0);
        }
        CP_COMMIT();

        const unsigned Ab = sbase + (c % 3) * STG_BYTES;
        const unsigned Bb = Ab + A_PL;
#pragma unroll
        for (int ks = 0; ks < 4; ++ks) {          // 4 sub-chunks of k=16
            unsigned Af[2][4];
            unsigned Bf[2][3][4];
#pragma unroll
            for (int mf = 0; mf < 2; ++mf) {
                unsigned off = (unsigned)((wm * 32 + mf * 16) * 128 + ks * 32) + aRowSel;
                ldsm_x4(Ab + swz128(off), Af[mf]);
            }
#pragma unroll
            for (int p = 0; p < 2; ++p)
#pragma unroll
                for (int g = 0; g < 3; ++g) {
                    unsigned off = (unsigned)((wn * 48 + g * 16) * 128 + ks * 32) + bRowSel;
                    ldsm_x4(Bb + p * B_PL + swz128(off), Bf[p][g]);
                }
#pragma unroll
            for (int mf = 0; mf < 2; ++mf)
#pragma unroll
                for (int nf = 0; nf < 6; ++nf) {
                    mma_f16(acc[mf][nf], Af[mf], &Bf[0][nf >> 1][(nf & 1) * 2]);
                    mma_f16(acc[mf][nf], Af[mf], &Bf[1][nf >> 1][(nf & 1) * 2]);
                }
        }
        __syncthreads();
    }

    // ---- epilogue: scale, bias + relu ----
#pragma unroll
    for (int mf = 0; mf < 2; ++mf) {
        int mlo = m0 + wm * 32 + mf * 16 + (lane >> 2);
        float szA = g_Zs[mlo];
        float szB = g_Zs[mlo + 8];
#pragma unroll
        for (int nf = 0; nf < 6; ++nf) {
            int n = n0 + wn * 48 + nf * 8 + 2 * (lane & 3);
            if (n < ODIM) {
                float sw0 = g_Ws[n], sw1 = g_Ws[n + 1];
                float b0 = bias[n], b1 = bias[n + 1];
                float2 v0, v1;
                v0.x = fmaxf(fmaf(acc[mf][nf][0], szA * sw0, b0), 0.f);
                v0.y = fmaxf(fmaf(acc[mf][nf][1], szA * sw1, b1), 0.f);
                v1.x = fmaxf(fmaf(acc[mf][nf][2], szB * sw0, b0), 0.f);
                v1.y = fmaxf(fmaf(acc[mf][nf][3], szB * sw1, b1), 0.f);
                *reinterpret_cast<float2*>(out + (size_t)mlo * ODIM + n) = v0;
                *reinterpret_cast<float2*>(out + (size_t)(mlo + 8) * ODIM + n) = v1;
            }
        }
    }
}

// ---------------------------------------------------------------------------
extern "C" void kernel_launch(void* const* d_in, const int* in_sizes, int n_in,
                              void* d_out, int out_size) {
    const float* x0  = (const float*)d_in[0];
    const float* x1  = (const float*)d_in[1];
    const float* s1  = (const float*)d_in[2];
    const float* s2  = (const float*)d_in[3];
    const float* Wm  = (const float*)d_in[4];
    const float* bia = (const float*)d_in[5];
    const int*   h1  = (const int*)d_in[6];
    const int*   h2  = (const int*)d_in[7];
    float* out = (float*)d_out;

    const int FFT_SMEM = (N_FFT + 128) * (int)sizeof(float2);  // 129 KB

    cudaFuncSetAttribute(fft_kernel<false>, cudaFuncAttributeMaxDynamicSharedMemorySize, FFT_SMEM);
    cudaFuncSetAttribute(fft_kernel<true>,  cudaFuncAttributeMaxDynamicSharedMemorySize, FFT_SMEM);
    cudaFuncSetAttribute(gemm_hmma_kernel, cudaFuncAttributeMaxDynamicSharedMemorySize, GEMM_SMEM);

    tw_init_kernel<<<(N_FFT + 255) / 256, 256>>>();

    const int n4 = BATCH * N_FFT * 2 / 4;
    zero_cbuf_kernel<<<(n4 + 255) / 256, 256>>>();

    sketch_kernel<<<(BATCH * D_IN + 255) / 256, 256>>>(x0, x1, s1, s2, h1, h2);

    wconv_kernel<<<OPAD, 256>>>(Wm);

    fft_kernel<false><<<BATCH, 512, FFT_SMEM>>>();
    fft_kernel<true><<<BATCH, 512, FFT_SMEM>>>();

    gemm_hmma_kernel<<<dim3((ODIM + 95) / 96, BATCH / 128), 256, GEMM_SMEM>>>(bia, out);
}

// round 10
// speedup vs baseline: 3.2508x; 1.3931x over previous
#include <cuda_runtime.h>
#include <cuda_fp16.h>
#include <cstdint>
#include <cstddef>
#include <math.h>

#define N_FFT   16000
#define BATCH   512
#define D_IN    2048
#define ODIM    3000
#define OPAD    3072
#define KDIM    16000

// Scratch (device globals — allocation-free per harness rules)
__device__ float2 g_CBUF[BATCH * N_FFT];               // 64 MB
__device__ float2 g_TW[N_FFT];                         // twiddles
__device__ __align__(16) __half g_Zh[BATCH * KDIM];    // 16 MB (z in fp16)
__device__ __align__(16) __half g_Wh[OPAD * KDIM];     // 96 MB (W in fp16)

static __device__ __forceinline__ float2 cmulf(float2 a, float2 b) {
    return make_float2(a.x * b.x - a.y * b.y, a.x * b.y + a.y * b.x);
}
static __device__ __forceinline__ unsigned smem_u32(const void* p) {
    unsigned a;
    asm("{ .reg .u64 t; cvta.to.shared.u64 t, %1; cvt.u32.u64 %0, t; }" : "=r"(a) : "l"(p));
    return a;
}
static __device__ __forceinline__ unsigned swz128(unsigned off) {
    return off ^ ((off >> 3) & 0x70);
}
#define CP_ASYNC16(dst, src) \
    asm volatile("cp.async.cg.shared.global [%0], [%1], 16;" :: "r"(dst), "l"(src))
#define CP_COMMIT() asm volatile("cp.async.commit_group;" ::: "memory")
#define CP_WAIT2()  asm volatile("cp.async.wait_group 2;" ::: "memory")

static __device__ __forceinline__ void ldsm_x4(unsigned addr, unsigned* r) {
    asm volatile("ldmatrix.sync.aligned.m8n8.x4.shared.b16 {%0,%1,%2,%3}, [%4];"
                 : "=r"(r[0]), "=r"(r[1]), "=r"(r[2]), "=r"(r[3]) : "r"(addr));
}
// fp16 HMMA m16n8k16, f32 accumulate
static __device__ __forceinline__ void mma_f16(float* c, const unsigned* a, const unsigned* b) {
    asm volatile(
        "mma.sync.aligned.m16n8k16.row.col.f32.f16.f16.f32 "
        "{%0,%1,%2,%3}, {%4,%5,%6,%7}, {%8,%9}, {%0,%1,%2,%3};"
        : "+f"(c[0]), "+f"(c[1]), "+f"(c[2]), "+f"(c[3])
        : "r"(a[0]), "r"(a[1]), "r"(a[2]), "r"(a[3]), "r"(b[0]), "r"(b[1]));
}

// ---------------------------------------------------------------------------
__global__ void tw_init_kernel() {
    int j = blockIdx.x * blockDim.x + threadIdx.x;
    if (j < N_FFT) {
        double ang = -2.0 * 3.14159265358979323846 * (double)j / (double)N_FFT;
        double s, c;
        sincos(ang, &s, &c);
        g_TW[j] = make_float2((float)c, (float)s);
    }
}

__global__ void zero_cbuf_kernel() {
    int i = blockIdx.x * blockDim.x + threadIdx.x;
    const int n4 = BATCH * N_FFT * 2 / 4;
    if (i < n4) {
        reinterpret_cast<float4*>(g_CBUF)[i] = make_float4(0.f, 0.f, 0.f, 0.f);
    }
}

// ---------------------------------------------------------------------------
// W -> fp16 plane (rows >= ODIM zero-filled). One thread = 8 elements.
// ---------------------------------------------------------------------------
__global__ __launch_bounds__(256) void wconv_kernel(const float* __restrict__ Wm) {
    const int SEG = KDIM / 8;                 // 2000
    int lin = blockIdx.x * blockDim.x + threadIdx.x;
    if (lin >= OPAD * SEG) return;
    int r = lin / SEG;
    int s = lin - r * SEG;
    __half2 h[4];
    if (r < ODIM) {
        const float4* p = reinterpret_cast<const float4*>(Wm + (size_t)r * KDIM + s * 8);
        float4 a = p[0], b = p[1];
        h[0] = __floats2half2_rn(a.x, a.y);
        h[1] = __floats2half2_rn(a.z, a.w);
        h[2] = __floats2half2_rn(b.x, b.y);
        h[3] = __floats2half2_rn(b.z, b.w);
    } else {
        h[0] = h[1] = h[2] = h[3] = __floats2half2_rn(0.f, 0.f);
    }
    *reinterpret_cast<uint4*>(g_Wh + (size_t)r * KDIM + s * 8) =
        *reinterpret_cast<uint4*>(h);
}

// ---------------------------------------------------------------------------
// Count sketch (packed complex c = p1 + i*p2)
// ---------------------------------------------------------------------------
__global__ void sketch_kernel(const float* __restrict__ x0, const float* __restrict__ x1,
                              const float* __restrict__ s1, const float* __restrict__ s2,
                              const int* __restrict__ h1, const int* __restrict__ h2) {
    int idx = blockIdx.x * blockDim.x + threadIdx.x;
    if (idx >= BATCH * D_IN) return;
    int b = idx / D_IN;
    int a = idx - b * D_IN;
    float v1 = s1[a] * x0[idx];
    float v2 = s2[a] * x1[idx];
    float2* row = g_CBUF + (size_t)b * N_FFT;
    atomicAdd(&row[h1[a]].x, v1);
    atomicAdd(&row[h2[a]].y, v2);
}

// ---------------------------------------------------------------------------
// 16000-pt complex FFT, one CTA per batch row, whole row in smem.
// N = 128 * 125.
//  Step A: radix-4 x3 + radix-2 over n1 (chunk q holds k1 = digitrev(q))
//  Step B: twiddle (folded into Step C stage 0)
//  Step C: radix-5 x3 per chunk (slot j holds k2 = rev5(j))
//  Output gathers (digit-reversed source) -> linear global stores.
//  INV epilogue: direct fp16 store of z = v.x / N.
// ---------------------------------------------------------------------------
template <bool INV>
__global__ __launch_bounds__(512) void fft_kernel() {
    extern __shared__ float2 sm[];
    float2* A    = sm;            // 16000
    float2* W125 = sm + N_FFT;    // 125

    const int b   = blockIdx.x;
    const int tid = threadIdx.x;
    const int T   = blockDim.x;   // 512
    float2* row = g_CBUF + (size_t)b * N_FFT;

    // ---- load phase ----
    if (!INV) {
        for (int k = tid; k < N_FFT; k += T) A[k] = row[k];
    } else {
        for (int k = tid; k < N_FFT; k += T) {
            float2 C = row[k];
            float2 D = row[k == 0 ? 0 : N_FFT - k];
            float2 F1 = make_float2(0.5f * (C.x + D.x), 0.5f * (C.y - D.y));
            float2 F2 = make_float2(0.5f * (C.y + D.y), 0.5f * (D.x - C.x));
            A[k] = cmulf(F1, F2);
        }
    }
    for (int m = tid; m < 125; m += T) {
        float2 t = g_TW[128 * m];        // W_125^m
        if (INV) t.y = -t.y;
        W125[m] = t;
    }
    __syncthreads();

    // ---- Step A: radix-4 x3 stages ----
    {
        const int subs4[3] = {32, 8, 2};
        const int twm[3]   = {125, 500, 2000};
#pragma unroll
        for (int s = 0; s < 3; ++s) {
            const int sub = subs4[s];
            const int L = 4 * sub;
            const int tm = twm[s];
            for (int i = tid; i < 4000; i += T) {
                int n2 = i % 125;
                int t  = i / 125;               // 0..31
                int blk = t / sub;
                int j   = t - blk * sub;
                int base = (blk * L + j) * 125 + n2;
                const int st = sub * 125;
                float2 x0 = A[base];
                float2 x1 = A[base + st];
                float2 x2 = A[base + 2 * st];
                float2 x3 = A[base + 3 * st];
                float2 t0 = make_float2(x0.x + x2.x, x0.y + x2.y);
                float2 t1 = make_float2(x0.x - x2.x, x0.y - x2.y);
                float2 t2 = make_float2(x1.x + x3.x, x1.y + x3.y);
                float2 t3 = make_float2(x1.x - x3.x, x1.y - x3.y);
                float2 it3 = INV ? make_float2(-t3.y, t3.x) : make_float2(t3.y, -t3.x);
                float2 y0 = make_float2(t0.x + t2.x, t0.y + t2.y);
                float2 y2 = make_float2(t0.x - t2.x, t0.y - t2.y);
                float2 y1 = make_float2(t1.x + it3.x, t1.y + it3.y);
                float2 y3 = make_float2(t1.x - it3.x, t1.y - it3.y);
                float2 w1 = g_TW[j * tm];
                float2 w2 = g_TW[2 * j * tm];
                float2 w3 = g_TW[3 * j * tm];
                if (INV) { w1.y = -w1.y; w2.y = -w2.y; w3.y = -w3.y; }
                A[base]          = y0;
                A[base + st]     = cmulf(y1, w1);
                A[base + 2 * st] = cmulf(y2, w2);
                A[base + 3 * st] = cmulf(y3, w3);
            }
            __syncthreads();
        }
        // final radix-2 stage (adjacent slots, no twiddle)
        for (int i = tid; i < 8000; i += T) {
            int n2 = i % 125;
            int m  = i / 125;                  // 0..63
            int p  = (2 * m) * 125 + n2;
            int p2 = p + 125;
            float2 u = A[p], v = A[p2];
            A[p]  = make_float2(u.x + v.x, u.y + v.y);
            A[p2] = make_float2(u.x - v.x, u.y - v.y);
        }
        __syncthreads();
    }

    // ---- Step C: 3 radix-5 DIF stages; stage 0 folds Step-B twiddle ----
    {
        const float c1 = 0.309016994374947424f;
        const float c2 = -0.809016994374947424f;
        const float S1 = INV ? -0.951056516295153572f : 0.951056516295153572f;
        const float S2 = INV ? -0.587785252292473129f : 0.587785252292473129f;
        const int Ls[3]   = {125, 25, 5};
        const int subs[3] = {25, 5, 1};
        const int fs[3]   = {1, 5, 25};
#pragma unroll
        for (int s = 0; s < 3; ++s) {
            const int L = Ls[s], sub = subs[s], f = fs[s];
            for (int i = tid; i < 3200; i += T) {
                int q = i / 25;
                int t = i - q * 25;
                int blk = t / sub;
                int j   = t - blk * sub;
                int base = q * 125 + blk * L + j;
                float2 x0 = A[base];
                float2 x1 = A[base + sub];
                float2 x2 = A[base + 2 * sub];
                float2 x3 = A[base + 3 * sub];
                float2 x4 = A[base + 4 * sub];
                if (s == 0) {
                    int k1 = (q >> 5) + ((q >> 3) & 3) * 4 + ((q >> 1) & 3) * 16 + (q & 1) * 64;
                    float2 b0 = g_TW[j * k1];
                    float2 b1 = g_TW[(j + 25) * k1];
                    float2 b2 = g_TW[(j + 50) * k1];
                    float2 b3 = g_TW[(j + 75) * k1];
                    float2 b4 = g_TW[(j + 100) * k1];
                    if (INV) { b0.y = -b0.y; b1.y = -b1.y; b2.y = -b2.y; b3.y = -b3.y; b4.y = -b4.y; }
                    x0 = cmulf(x0, b0);
                    x1 = cmulf(x1, b1);
                    x2 = cmulf(x2, b2);
                    x3 = cmulf(x3, b3);
                    x4 = cmulf(x4, b4);
                }
                float t1x = x1.x + x4.x, t1y = x1.y + x4.y;
                float t2x = x2.x + x3.x, t2y = x2.y + x3.y;
                float t3x = x1.x - x4.x, t3y = x1.y - x4.y;
                float t4x = x2.x - x3.x, t4y = x2.y - x3.y;
                float2 y0 = make_float2(x0.x + t1x + t2x, x0.y + t1y + t2y);
                float ax = x0.x + c1 * t1x + c2 * t2x;
                float ay = x0.y + c1 * t1y + c2 * t2y;
                float bx = S1 * t3x + S2 * t4x;
                float by = S1 * t3y + S2 * t4y;
                float dx = x0.x + c2 * t1x + c1 * t2x;
                float dy = x0.y + c2 * t1y + c1 * t2y;
                float ex = S2 * t3x - S1 * t4x;
                float ey = S2 * t3y - S1 * t4y;
                float2 y1 = make_float2(ax + by, ay - bx);
                float2 y4 = make_float2(ax - by, ay + bx);
                float2 y2 = make_float2(dx + ey, dy - ex);
                float2 y3 = make_float2(dx - ey, dy + ex);
                int jf = j * f;
                A[base]           = y0;
                A[base + sub]     = cmulf(y1, W125[jf]);
                A[base + 2 * sub] = cmulf(y2, W125[2 * jf]);
                A[base + 3 * sub] = cmulf(y3, W125[3 * jf]);
                A[base + 4 * sub] = cmulf(y4, W125[4 * jf]);
            }
            __syncthreads();
        }
    }

    // ---- output: gather from digit-reversed source, store linearly ----
    const float invN = 1.0f / (float)N_FFT;
    for (int k = tid; k < N_FFT; k += T) {
        int k1 = k & 127;
        int k2 = k >> 7;
        int q = (k1 & 3) * 32 + ((k1 >> 2) & 3) * 8 + ((k1 >> 4) & 3) * 2 + (k1 >> 6);
        int j = (k2 % 5) * 25 + ((k2 / 5) % 5) * 5 + (k2 / 25);
        float2 v = A[q * 125 + j];
        if (!INV) {
            row[k] = v;
        } else {
            g_Zh[(size_t)b * KDIM + k] = __float2half_rn(v.x * invN);
        }
    }
}

// ---------------------------------------------------------------------------
// fp16 single-term HMMA GEMM:  out = relu(zh @ wh^T + b)
// Tile 128x96, k-chunk 64, grid (32,4)=128 CTAs, 256 thr, 4-stage cp.async.
// Stage: A 16K | B 12K = 28 KB; x4 = 112 KB.
// ---------------------------------------------------------------------------
#define GTK 64
#define GITERS (KDIM / GTK)          // 250
#define A_PL 16384
#define B_PL 12288
#define STG_BYTES (A_PL + B_PL)      // 28672
#define NST 4
#define GEMM_SMEM (NST * STG_BYTES)  // 114688

static __device__ __forceinline__ void gemm_issue_stage(unsigned sb, int tid, int k0,
                                                        int m0, int n0g) {
    const char* zh = reinterpret_cast<const char*>(g_Zh);
    const char* wh = reinterpret_cast<const char*>(g_Wh);
#pragma unroll
    for (int i = 0; i < 4; ++i) {                 // A: 128 rows x 8 segs
        int lin = i * 256 + tid;
        int r = lin >> 3, seg = lin & 7;
        unsigned d = sb + swz128((unsigned)(r * 128 + seg * 16));
        size_t so = ((size_t)(m0 + r) * KDIM + k0 + seg * 8) * 2;
        CP_ASYNC16(d, zh + so);
    }
#pragma unroll
    for (int i = 0; i < 3; ++i) {                 // B: 96 rows x 8 segs
        int lin = i * 256 + tid;
        int r = lin >> 3, seg = lin & 7;
        unsigned d = sb + A_PL + swz128((unsigned)(r * 128 + seg * 16));
        size_t so = ((size_t)(n0g + r) * KDIM + k0 + seg * 8) * 2;
        CP_ASYNC16(d, wh + so);
    }
}

__global__ __launch_bounds__(256, 1) void gemm_hmma_kernel(const float* __restrict__ bias,
                                                           float* __restrict__ out) {
    extern __shared__ char gsm[];
    const unsigned sbase = smem_u32(gsm);
    const int tid  = threadIdx.x;
    const int lane = tid & 31;
    const int wid  = tid >> 5;
    const int wm   = wid >> 1;          // 0..3 -> 32 m rows each
    const int wn   = wid & 1;           // 0..1 -> 48 n cols each
    const int n0 = blockIdx.x * 96;
    const int m0 = blockIdx.y * 128;

    float acc[2][6][4];
#pragma unroll
    for (int i = 0; i < 2; ++i)
#pragma unroll
        for (int j = 0; j < 6; ++j)
#pragma unroll
            for (int e = 0; e < 4; ++e) acc[i][j][e] = 0.f;

    gemm_issue_stage(sbase, tid, 0, m0, n0);
    CP_COMMIT();
    gemm_issue_stage(sbase + STG_BYTES, tid, GTK, m0, n0);
    CP_COMMIT();
    gemm_issue_stage(sbase + 2 * STG_BYTES, tid, 2 * GTK, m0, n0);
    CP_COMMIT();

    const unsigned aRowSel = (unsigned)(lane & 15) * 128 + ((unsigned)(lane >> 4) << 4);
    const unsigned bRowSel = (unsigned)((lane & 7) | (((lane >> 4) & 1) << 3)) * 128 +
                             (((unsigned)(lane >> 3) & 1) << 4);

    for (int c = 0; c < GITERS; ++c) {
        CP_WAIT2();
        __syncthreads();
        if (c + 3 < GITERS) {
            gemm_issue_stage(sbase + ((c + 3) & 3) * STG_BYTES, tid, (c + 3) * GTK, m0, n0);
        }
        CP_COMMIT();

        const unsigned Ab = sbase + (c & 3) * STG_BYTES;
        const unsigned Bb = Ab + A_PL;
#pragma unroll
        for (int ks = 0; ks < 4; ++ks) {          // 4 sub-chunks of k=16
            unsigned Af[2][4];
            unsigned Bf[3][4];
#pragma unroll
            for (int mf = 0; mf < 2; ++mf) {
                unsigned off = (unsigned)((wm * 32 + mf * 16) * 128 + ks * 32) + aRowSel;
                ldsm_x4(Ab + swz128(off), Af[mf]);
            }
#pragma unroll
            for (int g = 0; g < 3; ++g) {
                unsigned off = (unsigned)((wn * 48 + g * 16) * 128 + ks * 32) + bRowSel;
                ldsm_x4(Bb + swz128(off), Bf[g]);
            }
#pragma unroll
            for (int mf = 0; mf < 2; ++mf)
#pragma unroll
                for (int nf = 0; nf < 6; ++nf)
                    mma_f16(acc[mf][nf], Af[mf], &Bf[nf >> 1][(nf & 1) * 2]);
        }
        __syncthreads();
    }

    // ---- epilogue: bias + relu ----
#pragma unroll
    for (int mf = 0; mf < 2; ++mf) {
        int mlo = m0 + wm * 32 + mf * 16 + (lane >> 2);
#pragma unroll
        for (int nf = 0; nf < 6; ++nf) {
            int n = n0 + wn * 48 + nf * 8 + 2 * (lane & 3);
            if (n < ODIM) {
                float b0 = bias[n], b1 = bias[n + 1];
                float2 v0, v1;
                v0.x = fmaxf(acc[mf][nf][0] + b0, 0.f);
                v0.y = fmaxf(acc[mf][nf][1] + b1, 0.f);
                v1.x = fmaxf(acc[mf][nf][2] + b0, 0.f);
                v1.y = fmaxf(acc[mf][nf][3] + b1, 0.f);
                *reinterpret_cast<float2*>(out + (size_t)mlo * ODIM + n) = v0;
                *reinterpret_cast<float2*>(out + (size_t)(mlo + 8) * ODIM + n) = v1;
            }
        }
    }
}

// ---------------------------------------------------------------------------
extern "C" void kernel_launch(void* const* d_in, const int* in_sizes, int n_in,
                              void* d_out, int out_size) {
    const float* x0  = (const float*)d_in[0];
    const float* x1  = (const float*)d_in[1];
    const float* s1  = (const float*)d_in[2];
    const float* s2  = (const float*)d_in[3];
    const float* Wm  = (const float*)d_in[4];
    const float* bia = (const float*)d_in[5];
    const int*   h1  = (const int*)d_in[6];
    const int*   h2  = (const int*)d_in[7];
    float* out = (float*)d_out;

    const int FFT_SMEM = (N_FFT + 128) * (int)sizeof(float2);  // 129 KB

    cudaFuncSetAttribute(fft_kernel<false>, cudaFuncAttributeMaxDynamicSharedMemorySize, FFT_SMEM);
    cudaFuncSetAttribute(fft_kernel<true>,  cudaFuncAttributeMaxDynamicSharedMemorySize, FFT_SMEM);
    cudaFuncSetAttribute(gemm_hmma_kernel, cudaFuncAttributeMaxDynamicSharedMemorySize, GEMM_SMEM);

    tw_init_kernel<<<(N_FFT + 255) / 256, 256>>>();

    const int n4 = BATCH * N_FFT * 2 / 4;
    zero_cbuf_kernel<<<(n4 + 255) / 256, 256>>>();

    sketch_kernel<<<(BATCH * D_IN + 255) / 256, 256>>>(x0, x1, s1, s2, h1, h2);

    const int wthreads = OPAD * (KDIM / 8);
    wconv_kernel<<<(wthreads + 255) / 256, 256>>>(Wm);

    fft_kernel<false><<<BATCH, 512, FFT_SMEM>>>();
    fft_kernel<true><<<BATCH, 512, FFT_SMEM>>>();

    gemm_hmma_kernel<<<dim3((ODIM + 95) / 96, BATCH / 128), 256, GEMM_SMEM>>>(bia, out);
}

// round 11
// speedup vs baseline: 3.6318x; 1.1172x over previous
#include <cuda_runtime.h>
#include <cuda_fp16.h>
#include <cstdint>
#include <cstddef>
#include <math.h>

#define N_FFT   16000
#define BATCH   512
#define D_IN    2048
#define ODIM    3000
#define OPAD    3072
#define KDIM    16000

// Scratch (device globals — allocation-free per harness rules)
__device__ float2 g_CBUF[BATCH * N_FFT];               // 64 MB (spectrum)
__device__ float2 g_TW[N_FFT];                         // twiddles
__device__ __align__(16) __half g_Zh[BATCH * KDIM];    // 16 MB (z in fp16)
__device__ __align__(16) __half g_Wh[OPAD * KDIM];     // 96 MB (W in fp16)

static __device__ __forceinline__ float2 cmulf(float2 a, float2 b) {
    return make_float2(a.x * b.x - a.y * b.y, a.x * b.y + a.y * b.x);
}
static __device__ __forceinline__ unsigned smem_u32(const void* p) {
    unsigned a;
    asm("{ .reg .u64 t; cvta.to.shared.u64 t, %1; cvt.u32.u64 %0, t; }" : "=r"(a) : "l"(p));
    return a;
}
static __device__ __forceinline__ unsigned swz128(unsigned off) {
    return off ^ ((off >> 3) & 0x70);
}
#define CP_ASYNC16(dst, src) \
    asm volatile("cp.async.cg.shared.global [%0], [%1], 16;" :: "r"(dst), "l"(src))
#define CP_COMMIT() asm volatile("cp.async.commit_group;" ::: "memory")
#define CP_WAIT2()  asm volatile("cp.async.wait_group 2;" ::: "memory")

static __device__ __forceinline__ void ldsm_x4(unsigned addr, unsigned* r) {
    asm volatile("ldmatrix.sync.aligned.m8n8.x4.shared.b16 {%0,%1,%2,%3}, [%4];"
                 : "=r"(r[0]), "=r"(r[1]), "=r"(r[2]), "=r"(r[3]) : "r"(addr));
}
// fp16 HMMA m16n8k16, f32 accumulate
static __device__ __forceinline__ void mma_f16(float* c, const unsigned* a, const unsigned* b) {
    asm volatile(
        "mma.sync.aligned.m16n8k16.row.col.f32.f16.f16.f32 "
        "{%0,%1,%2,%3}, {%4,%5,%6,%7}, {%8,%9}, {%0,%1,%2,%3};"
        : "+f"(c[0]), "+f"(c[1]), "+f"(c[2]), "+f"(c[3])
        : "r"(a[0]), "r"(a[1]), "r"(a[2]), "r"(a[3]), "r"(b[0]), "r"(b[1]));
}

// ---------------------------------------------------------------------------
__global__ void tw_init_kernel() {
    int j = blockIdx.x * blockDim.x + threadIdx.x;
    if (j < N_FFT) {
        double ang = -2.0 * 3.14159265358979323846 * (double)j / (double)N_FFT;
        double s, c;
        sincos(ang, &s, &c);
        g_TW[j] = make_float2((float)c, (float)s);
    }
}

// ---------------------------------------------------------------------------
// W -> fp16 plane (rows >= ODIM zero-filled). One thread = 8 elements.
// ---------------------------------------------------------------------------
__global__ __launch_bounds__(256) void wconv_kernel(const float* __restrict__ Wm) {
    const int SEG = KDIM / 8;                 // 2000
    int lin = blockIdx.x * blockDim.x + threadIdx.x;
    if (lin >= OPAD * SEG) return;
    int r = lin / SEG;
    int s = lin - r * SEG;
    __half2 h[4];
    if (r < ODIM) {
        const float4* p = reinterpret_cast<const float4*>(Wm + (size_t)r * KDIM + s * 8);
        float4 a = p[0], b = p[1];
        h[0] = __floats2half2_rn(a.x, a.y);
        h[1] = __floats2half2_rn(a.z, a.w);
        h[2] = __floats2half2_rn(b.x, b.y);
        h[3] = __floats2half2_rn(b.z, b.w);
    } else {
        h[0] = h[1] = h[2] = h[3] = __floats2half2_rn(0.f, 0.f);
    }
    *reinterpret_cast<uint4*>(g_Wh + (size_t)r * KDIM + s * 8) =
        *reinterpret_cast<uint4*>(h);
}

// ---------------------------------------------------------------------------
// 16000-pt complex FFT, one CTA (1024 thr) per batch row, row in smem.
// N = 128 * 125.
//  FWD (INV=false): fused count-sketch build (smem atomics) -> FFT -> spectrum
//  INV: load Z[k]=F1*F2 from spectrum -> inverse FFT -> fp16 z store
//  Step A: radix-4 x3 + radix-2 over n1 (chunk q holds k1 = digitrev(q))
//  Step B: twiddle (folded into Step C stage 0)
//  Step C: radix-5 x3 per chunk (slot j holds k2 = rev5(j))
//  Output gathers (digit-reversed source) -> linear global stores.
// ---------------------------------------------------------------------------
template <bool INV>
__global__ __launch_bounds__(1024) void fft_kernel(
    const float* __restrict__ x0, const float* __restrict__ x1,
    const float* __restrict__ s1, const float* __restrict__ s2,
    const int* __restrict__ h1, const int* __restrict__ h2) {
    extern __shared__ float2 sm[];
    float2* A    = sm;            // 16000
    float2* W125 = sm + N_FFT;    // 125

    const int b   = blockIdx.x;
    const int tid = threadIdx.x;
    const int T   = blockDim.x;   // 1024
    float2* row = g_CBUF + (size_t)b * N_FFT;

    // ---- load / build phase ----
    if (!INV) {
        // zero smem row, then scatter the count sketch with smem atomics
        for (int k = tid; k < N_FFT; k += T) A[k] = make_float2(0.f, 0.f);
        __syncthreads();
        for (int a = tid; a < D_IN; a += T) {
            float v1 = s1[a] * x0[b * D_IN + a];
            float v2 = s2[a] * x1[b * D_IN + a];
            atomicAdd(&A[h1[a]].x, v1);
            atomicAdd(&A[h2[a]].y, v2);
        }
    } else {
        for (int k = tid; k < N_FFT; k += T) {
            float2 C = row[k];
            float2 D = row[k == 0 ? 0 : N_FFT - k];
            float2 F1 = make_float2(0.5f * (C.x + D.x), 0.5f * (C.y - D.y));
            float2 F2 = make_float2(0.5f * (C.y + D.y), 0.5f * (D.x - C.x));
            A[k] = cmulf(F1, F2);
        }
    }
    for (int m = tid; m < 125; m += T) {
        float2 t = g_TW[128 * m];        // W_125^m
        if (INV) t.y = -t.y;
        W125[m] = t;
    }
    __syncthreads();

    // ---- Step A: radix-4 x3 stages ----
    {
        const int subs4[3] = {32, 8, 2};
        const int twm[3]   = {125, 500, 2000};
#pragma unroll
        for (int s = 0; s < 3; ++s) {
            const int sub = subs4[s];
            const int L = 4 * sub;
            const int tm = twm[s];
            for (int i = tid; i < 4000; i += T) {
                int n2 = i % 125;
                int t  = i / 125;               // 0..31
                int blk = t / sub;
                int j   = t - blk * sub;
                int base = (blk * L + j) * 125 + n2;
                const int st = sub * 125;
                float2 x0v = A[base];
                float2 x1v = A[base + st];
                float2 x2v = A[base + 2 * st];
                float2 x3v = A[base + 3 * st];
                float2 t0 = make_float2(x0v.x + x2v.x, x0v.y + x2v.y);
                float2 t1 = make_float2(x0v.x - x2v.x, x0v.y - x2v.y);
                float2 t2 = make_float2(x1v.x + x3v.x, x1v.y + x3v.y);
                float2 t3 = make_float2(x1v.x - x3v.x, x1v.y - x3v.y);
                float2 it3 = INV ? make_float2(-t3.y, t3.x) : make_float2(t3.y, -t3.x);
                float2 y0 = make_float2(t0.x + t2.x, t0.y + t2.y);
                float2 y2 = make_float2(t0.x - t2.x, t0.y - t2.y);
                float2 y1 = make_float2(t1.x + it3.x, t1.y + it3.y);
                float2 y3 = make_float2(t1.x - it3.x, t1.y - it3.y);
                float2 w1 = g_TW[j * tm];
                float2 w2 = g_TW[2 * j * tm];
                float2 w3 = g_TW[3 * j * tm];
                if (INV) { w1.y = -w1.y; w2.y = -w2.y; w3.y = -w3.y; }
                A[base]          = y0;
                A[base + st]     = cmulf(y1, w1);
                A[base + 2 * st] = cmulf(y2, w2);
                A[base + 3 * st] = cmulf(y3, w3);
            }
            __syncthreads();
        }
        // final radix-2 stage (adjacent slots, no twiddle)
        for (int i = tid; i < 8000; i += T) {
            int n2 = i % 125;
            int m  = i / 125;                  // 0..63
            int p  = (2 * m) * 125 + n2;
            int p2 = p + 125;
            float2 u = A[p], v = A[p2];
            A[p]  = make_float2(u.x + v.x, u.y + v.y);
            A[p2] = make_float2(u.x - v.x, u.y - v.y);
        }
        __syncthreads();
    }

    // ---- Step C: 3 radix-5 DIF stages; stage 0 folds Step-B twiddle ----
    {
        const float c1 = 0.309016994374947424f;
        const float c2 = -0.809016994374947424f;
        const float S1 = INV ? -0.951056516295153572f : 0.951056516295153572f;
        const float S2 = INV ? -0.587785252292473129f : 0.587785252292473129f;
        const int Ls[3]   = {125, 25, 5};
        const int subs[3] = {25, 5, 1};
        const int fs[3]   = {1, 5, 25};
#pragma unroll
        for (int s = 0; s < 3; ++s) {
            const int L = Ls[s], sub = subs[s], f = fs[s];
            for (int i = tid; i < 3200; i += T) {
                int q = i / 25;
                int t = i - q * 25;
                int blk = t / sub;
                int j   = t - blk * sub;
                int base = q * 125 + blk * L + j;
                float2 x0v = A[base];
                float2 x1v = A[base + sub];
                float2 x2v = A[base + 2 * sub];
                float2 x3v = A[base + 3 * sub];
                float2 x4v = A[base + 4 * sub];
                if (s == 0) {
                    int k1 = (q >> 5) + ((q >> 3) & 3) * 4 + ((q >> 1) & 3) * 16 + (q & 1) * 64;
                    float2 b0 = g_TW[j * k1];
                    float2 b1 = g_TW[(j + 25) * k1];
                    float2 b2 = g_TW[(j + 50) * k1];
                    float2 b3 = g_TW[(j + 75) * k1];
                    float2 b4 = g_TW[(j + 100) * k1];
                    if (INV) { b0.y = -b0.y; b1.y = -b1.y; b2.y = -b2.y; b3.y = -b3.y; b4.y = -b4.y; }
                    x0v = cmulf(x0v, b0);
                    x1v = cmulf(x1v, b1);
                    x2v = cmulf(x2v, b2);
                    x3v = cmulf(x3v, b3);
                    x4v = cmulf(x4v, b4);
                }
                float t1x = x1v.x + x4v.x, t1y = x1v.y + x4v.y;
                float t2x = x2v.x + x3v.x, t2y = x2v.y + x3v.y;
                float t3x = x1v.x - x4v.x, t3y = x1v.y - x4v.y;
                float t4x = x2v.x - x3v.x, t4y = x2v.y - x3v.y;
                float2 y0 = make_float2(x0v.x + t1x + t2x, x0v.y + t1y + t2y);
                float ax = x0v.x + c1 * t1x + c2 * t2x;
                float ay = x0v.y + c1 * t1y + c2 * t2y;
                float bx = S1 * t3x + S2 * t4x;
                float by = S1 * t3y + S2 * t4y;
                float dx = x0v.x + c2 * t1x + c1 * t2x;
                float dy = x0v.y + c2 * t1y + c1 * t2y;
                float ex = S2 * t3x - S1 * t4x;
                float ey = S2 * t3y - S1 * t4y;
                float2 y1 = make_float2(ax + by, ay - bx);
                float2 y4 = make_float2(ax - by, ay + bx);
                float2 y2 = make_float2(dx + ey, dy - ex);
                float2 y3 = make_float2(dx - ey, dy + ex);
                int jf = j * f;
                A[base]           = y0;
                A[base + sub]     = cmulf(y1, W125[jf]);
                A[base + 2 * sub] = cmulf(y2, W125[2 * jf]);
                A[base + 3 * sub] = cmulf(y3, W125[3 * jf]);
                A[base + 4 * sub] = cmulf(y4, W125[4 * jf]);
            }
            __syncthreads();
        }
    }

    // ---- output: gather from digit-reversed source, store linearly ----
    const float invN = 1.0f / (float)N_FFT;
    for (int k = tid; k < N_FFT; k += T) {
        int k1 = k & 127;
        int k2 = k >> 7;
        int q = (k1 & 3) * 32 + ((k1 >> 2) & 3) * 8 + ((k1 >> 4) & 3) * 2 + (k1 >> 6);
        int j = (k2 % 5) * 25 + ((k2 / 5) % 5) * 5 + (k2 / 25);
        float2 v = A[q * 125 + j];
        if (!INV) {
            row[k] = v;
        } else {
            g_Zh[(size_t)b * KDIM + k] = __float2half_rn(v.x * invN);
        }
    }
}

// ---------------------------------------------------------------------------
// fp16 single-term HMMA GEMM:  out = relu(zh @ wh^T + b)
// Tile 128x96, k-chunk 64, grid (32,4)=128 CTAs, 256 thr, 4-stage cp.async.
// ---------------------------------------------------------------------------
#define GTK 64
#define GITERS (KDIM / GTK)          // 250
#define A_PL 16384
#define B_PL 12288
#define STG_BYTES (A_PL + B_PL)      // 28672
#define NST 4
#define GEMM_SMEM (NST * STG_BYTES)  // 114688

static __device__ __forceinline__ void gemm_issue_stage(unsigned sb, int tid, int k0,
                                                        int m0, int n0g) {
    const char* zh = reinterpret_cast<const char*>(g_Zh);
    const char* wh = reinterpret_cast<const char*>(g_Wh);
#pragma unroll
    for (int i = 0; i < 4; ++i) {                 // A: 128 rows x 8 segs
        int lin = i * 256 + tid;
        int r = lin >> 3, seg = lin & 7;
        unsigned d = sb + swz128((unsigned)(r * 128 + seg * 16));
        size_t so = ((size_t)(m0 + r) * KDIM + k0 + seg * 8) * 2;
        CP_ASYNC16(d, zh + so);
    }
#pragma unroll
    for (int i = 0; i < 3; ++i) {                 // B: 96 rows x 8 segs
        int lin = i * 256 + tid;
        int r = lin >> 3, seg = lin & 7;
        unsigned d = sb + A_PL + swz128((unsigned)(r * 128 + seg * 16));
        size_t so = ((size_t)(n0g + r) * KDIM + k0 + seg * 8) * 2;
        CP_ASYNC16(d, wh + so);
    }
}

__global__ __launch_bounds__(256, 1) void gemm_hmma_kernel(const float* __restrict__ bias,
                                                           float* __restrict__ out) {
    extern __shared__ char gsm[];
    const unsigned sbase = smem_u32(gsm);
    const int tid  = threadIdx.x;
    const int lane = tid & 31;
    const int wid  = tid >> 5;
    const int wm   = wid >> 1;          // 0..3 -> 32 m rows each
    const int wn   = wid & 1;           // 0..1 -> 48 n cols each
    const int n0 = blockIdx.x * 96;
    const int m0 = blockIdx.y * 128;

    float acc[2][6][4];
#pragma unroll
    for (int i = 0; i < 2; ++i)
#pragma unroll
        for (int j = 0; j < 6; ++j)
#pragma unroll
            for (int e = 0; e < 4; ++e) acc[i][j][e] = 0.f;

    gemm_issue_stage(sbase, tid, 0, m0, n0);
    CP_COMMIT();
    gemm_issue_stage(sbase + STG_BYTES, tid, GTK, m0, n0);
    CP_COMMIT();
    gemm_issue_stage(sbase + 2 * STG_BYTES, tid, 2 * GTK, m0, n0);
    CP_COMMIT();

    const unsigned aRowSel = (unsigned)(lane & 15) * 128 + ((unsigned)(lane >> 4) << 4);
    const unsigned bRowSel = (unsigned)((lane & 7) | (((lane >> 4) & 1) << 3)) * 128 +
                             (((unsigned)(lane >> 3) & 1) << 4);

    for (int c = 0; c < GITERS; ++c) {
        CP_WAIT2();
        __syncthreads();
        if (c + 3 < GITERS) {
            gemm_issue_stage(sbase + ((c + 3) & 3) * STG_BYTES, tid, (c + 3) * GTK, m0, n0);
        }
        CP_COMMIT();

        const unsigned Ab = sbase + (c & 3) * STG_BYTES;
        const unsigned Bb = Ab + A_PL;
#pragma unroll
        for (int ks = 0; ks < 4; ++ks) {          // 4 sub-chunks of k=16
            unsigned Af[2][4];
            unsigned Bf[3][4];
#pragma unroll
            for (int mf = 0; mf < 2; ++mf) {
                unsigned off = (unsigned)((wm * 32 + mf * 16) * 128 + ks * 32) + aRowSel;
                ldsm_x4(Ab + swz128(off), Af[mf]);
            }
#pragma unroll
            for (int g = 0; g < 3; ++g) {
                unsigned off = (unsigned)((wn * 48 + g * 16) * 128 + ks * 32) + bRowSel;
                ldsm_x4(Bb + swz128(off), Bf[g]);
            }
#pragma unroll
            for (int mf = 0; mf < 2; ++mf)
#pragma unroll
                for (int nf = 0; nf < 6; ++nf)
                    mma_f16(acc[mf][nf], Af[mf], &Bf[nf >> 1][(nf & 1) * 2]);
        }
        __syncthreads();
    }

    // ---- epilogue: bias + relu ----
#pragma unroll
    for (int mf = 0; mf < 2; ++mf) {
        int mlo = m0 + wm * 32 + mf * 16 + (lane >> 2);
#pragma unroll
        for (int nf = 0; nf < 6; ++nf) {
            int n = n0 + wn * 48 + nf * 8 + 2 * (lane & 3);
            if (n < ODIM) {
                float b0 = bias[n], b1 = bias[n + 1];
                float2 v0, v1;
                v0.x = fmaxf(acc[mf][nf][0] + b0, 0.f);
                v0.y = fmaxf(acc[mf][nf][1] + b1, 0.f);
                v1.x = fmaxf(acc[mf][nf][2] + b0, 0.f);
                v1.y = fmaxf(acc[mf][nf][3] + b1, 0.f);
                *reinterpret_cast<float2*>(out + (size_t)mlo * ODIM + n) = v0;
                *reinterpret_cast<float2*>(out + (size_t)(mlo + 8) * ODIM + n) = v1;
            }
        }
    }
}

// ---------------------------------------------------------------------------
extern "C" void kernel_launch(void* const* d_in, const int* in_sizes, int n_in,
                              void* d_out, int out_size) {
    const float* x0  = (const float*)d_in[0];
    const float* x1  = (const float*)d_in[1];
    const float* s1  = (const float*)d_in[2];
    const float* s2  = (const float*)d_in[3];
    const float* Wm  = (const float*)d_in[4];
    const float* bia = (const float*)d_in[5];
    const int*   h1  = (const int*)d_in[6];
    const int*   h2  = (const int*)d_in[7];
    float* out = (float*)d_out;

    const int FFT_SMEM = (N_FFT + 128) * (int)sizeof(float2);  // 129 KB

    cudaFuncSetAttribute(fft_kernel<false>, cudaFuncAttributeMaxDynamicSharedMemorySize, FFT_SMEM);
    cudaFuncSetAttribute(fft_kernel<true>,  cudaFuncAttributeMaxDynamicSharedMemorySize, FFT_SMEM);
    cudaFuncSetAttribute(gemm_hmma_kernel, cudaFuncAttributeMaxDynamicSharedMemorySize, GEMM_SMEM);

    tw_init_kernel<<<(N_FFT + 255) / 256, 256>>>();

    const int wthreads = OPAD * (KDIM / 8);
    wconv_kernel<<<(wthreads + 255) / 256, 256>>>(Wm);

    fft_kernel<false><<<BATCH, 1024, FFT_SMEM>>>(x0, x1, s1, s2, h1, h2);
    fft_kernel<true><<<BATCH, 1024, FFT_SMEM>>>(x0, x1, s1, s2, h1, h2);

    gemm_hmma_kernel<<<dim3((ODIM + 95) / 96, BATCH / 128), 256, GEMM_SMEM>>>(bia, out);
}

// round 12
// speedup vs baseline: 3.9530x; 1.0884x over previous
#include <cuda_runtime.h>
#include <cuda_fp16.h>
#include <cstdint>
#include <cstddef>
#include <math.h>

#define N_FFT   16000
#define BATCH   512
#define D_IN    2048
#define ODIM    3000
#define OPAD    3072
#define KDIM    16000

// Scratch (device globals — allocation-free per harness rules)
__device__ float2 g_TW[N_FFT];                         // twiddles
__device__ __align__(16) __half g_Zh[BATCH * KDIM];    // 16 MB (z in fp16)
__device__ __align__(16) __half g_Wh[OPAD * KDIM];     // 96 MB (W in fp16)

static __device__ __forceinline__ float2 cmulf(float2 a, float2 b) {
    return make_float2(a.x * b.x - a.y * b.y, a.x * b.y + a.y * b.x);
}
static __device__ __forceinline__ unsigned smem_u32(const void* p) {
    unsigned a;
    asm("{ .reg .u64 t; cvta.to.shared.u64 t, %1; cvt.u32.u64 %0, t; }" : "=r"(a) : "l"(p));
    return a;
}
static __device__ __forceinline__ unsigned swz128(unsigned off) {
    return off ^ ((off >> 3) & 0x70);
}
#define CP_ASYNC16(dst, src) \
    asm volatile("cp.async.cg.shared.global [%0], [%1], 16;" :: "r"(dst), "l"(src))
#define CP_COMMIT() asm volatile("cp.async.commit_group;" ::: "memory")
#define CP_WAIT2()  asm volatile("cp.async.wait_group 2;" ::: "memory")

static __device__ __forceinline__ void ldsm_x4(unsigned addr, unsigned* r) {
    asm volatile("ldmatrix.sync.aligned.m8n8.x4.shared.b16 {%0,%1,%2,%3}, [%4];"
                 : "=r"(r[0]), "=r"(r[1]), "=r"(r[2]), "=r"(r[3]) : "r"(addr));
}
static __device__ __forceinline__ void mma_f16(float* c, const unsigned* a, const unsigned* b) {
    asm volatile(
        "mma.sync.aligned.m16n8k16.row.col.f32.f16.f16.f32 "
        "{%0,%1,%2,%3}, {%4,%5,%6,%7}, {%8,%9}, {%0,%1,%2,%3};"
        : "+f"(c[0]), "+f"(c[1]), "+f"(c[2]), "+f"(c[3])
        : "r"(a[0]), "r"(a[1]), "r"(a[2]), "r"(a[3]), "r"(b[0]), "r"(b[1]));
}

// ---------------------------------------------------------------------------
__global__ void tw_init_kernel() {
    int j = blockIdx.x * blockDim.x + threadIdx.x;
    if (j < N_FFT) {
        double ang = -2.0 * 3.14159265358979323846 * (double)j / (double)N_FFT;
        double s, c;
        sincos(ang, &s, &c);
        g_TW[j] = make_float2((float)c, (float)s);
    }
}

// ---------------------------------------------------------------------------
// W -> fp16 plane (rows >= ODIM zero-filled). One thread = 8 elements.
// ---------------------------------------------------------------------------
__global__ __launch_bounds__(256) void wconv_kernel(const float* __restrict__ Wm) {
    const int SEG = KDIM / 8;                 // 2000
    int lin = blockIdx.x * blockDim.x + threadIdx.x;
    if (lin >= OPAD * SEG) return;
    int r = lin / SEG;
    int s = lin - r * SEG;
    __half2 h[4];
    if (r < ODIM) {
        const float4* p = reinterpret_cast<const float4*>(Wm + (size_t)r * KDIM + s * 8);
        float4 a = p[0], b = p[1];
        h[0] = __floats2half2_rn(a.x, a.y);
        h[1] = __floats2half2_rn(a.z, a.w);
        h[2] = __floats2half2_rn(b.x, b.y);
        h[3] = __floats2half2_rn(b.z, b.w);
    } else {
        h[0] = h[1] = h[2] = h[3] = __floats2half2_rn(0.f, 0.f);
    }
    *reinterpret_cast<uint4*>(g_Wh + (size_t)r * KDIM + s * 8) =
        *reinterpret_cast<uint4*>(h);
}

// ---------------------------------------------------------------------------
// FFT core: Step A (radix-4 x2 + radix-8) + Step C (radix-5 x3, stage 0 folds
// the inter-step twiddle). Data layout after core: slot s = q*125 + j holds
// spectrum index k = k1(q) + 128*k2(j), k1(q) = (q>>5)+((q>>3)&3)*4+(q&7)*16,
// k2(j) = rev5(j).
// ---------------------------------------------------------------------------
template <bool INV>
static __device__ __forceinline__ void fft_core(float2* A, const float2* W125,
                                                int tid, int T) {
    // ---- Step A: radix-4 x2 ----
    {
        const int subs4[2] = {32, 8};
        const int twm[2]   = {125, 500};
#pragma unroll
        for (int s = 0; s < 2; ++s) {
            const int sub = subs4[s];
            const int L = 4 * sub;
            const int tm = twm[s];
            for (int i = tid; i < 4000; i += T) {
                int n2 = i % 125;
                int t  = i / 125;               // 0..31
                int blk = t / sub;
                int j   = t - blk * sub;
                int base = (blk * L + j) * 125 + n2;
                const int st = sub * 125;
                float2 x0v = A[base];
                float2 x1v = A[base + st];
                float2 x2v = A[base + 2 * st];
                float2 x3v = A[base + 3 * st];
                float2 t0 = make_float2(x0v.x + x2v.x, x0v.y + x2v.y);
                float2 t1 = make_float2(x0v.x - x2v.x, x0v.y - x2v.y);
                float2 t2 = make_float2(x1v.x + x3v.x, x1v.y + x3v.y);
                float2 t3 = make_float2(x1v.x - x3v.x, x1v.y - x3v.y);
                float2 it3 = INV ? make_float2(-t3.y, t3.x) : make_float2(t3.y, -t3.x);
                float2 y0 = make_float2(t0.x + t2.x, t0.y + t2.y);
                float2 y2 = make_float2(t0.x - t2.x, t0.y - t2.y);
                float2 y1 = make_float2(t1.x + it3.x, t1.y + it3.y);
                float2 y3 = make_float2(t1.x - it3.x, t1.y - it3.y);
                float2 w1 = g_TW[j * tm];
                float2 w2 = g_TW[2 * j * tm];
                float2 w3 = g_TW[3 * j * tm];
                if (INV) { w1.y = -w1.y; w2.y = -w2.y; w3.y = -w3.y; }
                A[base]          = y0;
                A[base + st]     = cmulf(y1, w1);
                A[base + 2 * st] = cmulf(y2, w2);
                A[base + 3 * st] = cmulf(y3, w3);
            }
            __syncthreads();
        }
    }
    // ---- Step A final: radix-8 (direct 8-pt DFT, no post-twiddles) ----
    {
        const float h8 = 0.70710678118654752440f;
        for (int i = tid; i < 2000; i += T) {
            int n2 = i % 125;
            int m  = i / 125;                  // 0..15
            int base = m * 1000 + n2;
            float2 x[8];
#pragma unroll
            for (int e = 0; e < 8; ++e) x[e] = A[base + e * 125];
            // even part (x0,x2,x4,x6)
            float2 s0 = make_float2(x[0].x + x[4].x, x[0].y + x[4].y);
            float2 s1 = make_float2(x[0].x - x[4].x, x[0].y - x[4].y);
            float2 s2 = make_float2(x[2].x + x[6].x, x[2].y + x[6].y);
            float2 s3 = make_float2(x[2].x - x[6].x, x[2].y - x[6].y);
            float2 E0 = make_float2(s0.x + s2.x, s0.y + s2.y);
            float2 E2 = make_float2(s0.x - s2.x, s0.y - s2.y);
            float2 E1 = INV ? make_float2(s1.x - s3.y, s1.y + s3.x)
                            : make_float2(s1.x + s3.y, s1.y - s3.x);
            float2 E3 = INV ? make_float2(s1.x + s3.y, s1.y - s3.x)
                            : make_float2(s1.x - s3.y, s1.y + s3.x);
            // odd part (x1,x3,x5,x7)
            float2 t0 = make_float2(x[1].x + x[5].x, x[1].y + x[5].y);
            float2 t1 = make_float2(x[1].x - x[5].x, x[1].y - x[5].y);
            float2 t2 = make_float2(x[3].x + x[7].x, x[3].y + x[7].y);
            float2 t3 = make_float2(x[3].x - x[7].x, x[3].y - x[7].y);
            float2 O0 = make_float2(t0.x + t2.x, t0.y + t2.y);
            float2 O2 = make_float2(t0.x - t2.x, t0.y - t2.y);
            float2 O1 = INV ? make_float2(t1.x - t3.y, t1.y + t3.x)
                            : make_float2(t1.x + t3.y, t1.y - t3.x);
            float2 O3 = INV ? make_float2(t1.x + t3.y, t1.y - t3.x)
                            : make_float2(t1.x - t3.y, t1.y + t3.x);
            // twiddle odd by W8^k
            float2 W1O, W2O, W3O;
            if (!INV) {
                W1O = make_float2(h8 * (O1.x + O1.y), h8 * (O1.y - O1.x));
                W2O = make_float2(O2.y, -O2.x);
                W3O = make_float2(-h8 * (O3.x - O3.y), -h8 * (O3.x + O3.y));
            } else {
                W1O = make_float2(h8 * (O1.x - O1.y), h8 * (O1.y + O1.x));
                W2O = make_float2(-O2.y, O2.x);
                W3O = make_float2(-h8 * (O3.x + O3.y), -h8 * (O3.y - O3.x));
            }
            A[base]           = make_float2(E0.x + O0.x, E0.y + O0.y);
            A[base + 125]     = make_float2(E1.x + W1O.x, E1.y + W1O.y);
            A[base + 250]     = make_float2(E2.x + W2O.x, E2.y + W2O.y);
            A[base + 375]     = make_float2(E3.x + W3O.x, E3.y + W3O.y);
            A[base + 500]     = make_float2(E0.x - O0.x, E0.y - O0.y);
            A[base + 625]     = make_float2(E1.x - W1O.x, E1.y - W1O.y);
            A[base + 750]     = make_float2(E2.x - W2O.x, E2.y - W2O.y);
            A[base + 875]     = make_float2(E3.x - W3O.x, E3.y - W3O.y);
        }
        __syncthreads();
    }
    // ---- Step C: 3 radix-5 DIF stages; stage 0 folds inter-step twiddle ----
    {
        const float c1 = 0.309016994374947424f;
        const float c2 = -0.809016994374947424f;
        const float S1 = INV ? -0.951056516295153572f : 0.951056516295153572f;
        const float S2 = INV ? -0.587785252292473129f : 0.587785252292473129f;
        const int Ls[3]   = {125, 25, 5};
        const int subs[3] = {25, 5, 1};
        const int fs[3]   = {1, 5, 25};
#pragma unroll
        for (int s = 0; s < 3; ++s) {
            const int L = Ls[s], sub = subs[s], f = fs[s];
            for (int i = tid; i < 3200; i += T) {
                int q = i / 25;
                int t = i - q * 25;
                int blk = t / sub;
                int j   = t - blk * sub;
                int base = q * 125 + blk * L + j;
                float2 x0v = A[base];
                float2 x1v = A[base + sub];
                float2 x2v = A[base + 2 * sub];
                float2 x3v = A[base + 3 * sub];
                float2 x4v = A[base + 4 * sub];
                if (s == 0) {
                    int k1 = (q >> 5) + ((q >> 3) & 3) * 4 + (q & 7) * 16;
                    float2 b0 = g_TW[j * k1];
                    float2 b1 = g_TW[(j + 25) * k1];
                    float2 b2 = g_TW[(j + 50) * k1];
                    float2 b3 = g_TW[(j + 75) * k1];
                    float2 b4 = g_TW[(j + 100) * k1];
                    if (INV) { b0.y = -b0.y; b1.y = -b1.y; b2.y = -b2.y; b3.y = -b3.y; b4.y = -b4.y; }
                    x0v = cmulf(x0v, b0);
                    x1v = cmulf(x1v, b1);
                    x2v = cmulf(x2v, b2);
                    x3v = cmulf(x3v, b3);
                    x4v = cmulf(x4v, b4);
                }
                float t1x = x1v.x + x4v.x, t1y = x1v.y + x4v.y;
                float t2x = x2v.x + x3v.x, t2y = x2v.y + x3v.y;
                float t3x = x1v.x - x4v.x, t3y = x1v.y - x4v.y;
                float t4x = x2v.x - x3v.x, t4y = x2v.y - x3v.y;
                float2 y0 = make_float2(x0v.x + t1x + t2x, x0v.y + t1y + t2y);
                float ax = x0v.x + c1 * t1x + c2 * t2x;
                float ay = x0v.y + c1 * t1y + c2 * t2y;
                float bx = S1 * t3x + S2 * t4x;
                float by = S1 * t3y + S2 * t4y;
                float dx = x0v.x + c2 * t1x + c1 * t2x;
                float dy = x0v.y + c2 * t1y + c1 * t2y;
                float ex = S2 * t3x - S1 * t4x;
                float ey = S2 * t3y - S1 * t4y;
                float2 y1 = make_float2(ax + by, ay - bx);
                float2 y4 = make_float2(ax - by, ay + bx);
                float2 y2 = make_float2(dx + ey, dy - ex);
                float2 y3 = make_float2(dx - ey, dy + ex);
                int jf = j * f;
                float2 w1 = W125[jf],  w2 = W125[2 * jf], w3 = W125[3 * jf], w4 = W125[4 * jf];
                if (INV) { w1.y = -w1.y; w2.y = -w2.y; w3.y = -w3.y; w4.y = -w4.y; }
                A[base]           = y0;
                A[base + sub]     = cmulf(y1, w1);
                A[base + 2 * sub] = cmulf(y2, w2);
                A[base + 3 * sub] = cmulf(y3, w3);
                A[base + 4 * sub] = cmulf(y4, w4);
            }
            __syncthreads();
        }
    }
}

// slot of spectrum index k in post-core layout
static __device__ __forceinline__ int slot_of(int k) {
    int k1 = k & 127;
    int k2 = k >> 7;
    int q = (k1 & 3) * 32 + ((k1 >> 2) & 3) * 8 + (k1 >> 4);
    int j = (k2 / 25) + ((k2 / 5) % 5) * 5 + (k2 % 5) * 25;
    return q * 125 + j;
}

// ---------------------------------------------------------------------------
// Fully fused: sketch build -> fwd FFT -> pointwise (via conj symmetry) ->
// inverse FFT -> fp16 z store. One CTA (1024 thr) per batch row.
// ---------------------------------------------------------------------------
__global__ __launch_bounds__(1024) void fused_fft_kernel(
    const float* __restrict__ x0, const float* __restrict__ x1,
    const float* __restrict__ s1, const float* __restrict__ s2,
    const int* __restrict__ h1, const int* __restrict__ h2) {
    extern __shared__ float2 sm[];
    float2* A    = sm;            // 16000
    float2* W125 = sm + N_FFT;    // 125

    const int b   = blockIdx.x;
    const int tid = threadIdx.x;
    const int T   = blockDim.x;   // 1024

    // ---- build count sketch in smem (packed complex p1 + i*p2) ----
    for (int k = tid; k < N_FFT; k += T) A[k] = make_float2(0.f, 0.f);
    for (int m = tid; m < 125; m += T) W125[m] = g_TW[128 * m];
    __syncthreads();
    for (int a = tid; a < D_IN; a += T) {
        float v1 = s1[a] * x0[b * D_IN + a];
        float v2 = s2[a] * x1[b * D_IN + a];
        atomicAdd(&A[h1[a]].x, v1);
        atomicAdd(&A[h2[a]].y, v2);
    }
    __syncthreads();

    // ---- forward FFT ----
    fft_core<false>(A, W125, tid, T);

    // ---- pointwise: Z[k] = F1[k]*F2[k]; Z[N-k] = conj(Z[k]) ----
    {
        float2 Zreg[8];
#pragma unroll
        for (int it = 0; it < 8; ++it) {
            int k = tid + it * T;
            if (k <= 8000) {
                int sA = slot_of(k);
                int kn = (k == 0) ? 0 : N_FFT - k;
                int sB = (kn == k) ? sA : slot_of(kn);
                float2 C = A[sA], D = A[sB];
                float2 F1 = make_float2(0.5f * (C.x + D.x), 0.5f * (C.y - D.y));
                float2 F2 = make_float2(0.5f * (C.y + D.y), 0.5f * (D.x - C.x));
                Zreg[it] = cmulf(F1, F2);
            }
        }
        __syncthreads();
#pragma unroll
        for (int it = 0; it < 8; ++it) {
            int k = tid + it * T;
            if (k <= 8000) {
                float2 Z = Zreg[it];
                A[k] = Z;                                   // natural slot
                if (k > 0 && k < 8000)
                    A[N_FFT - k] = make_float2(Z.x, -Z.y);  // conj symmetry
            }
        }
        __syncthreads();
    }

    // ---- inverse FFT ----
    fft_core<true>(A, W125, tid, T);

    // ---- output: gather digit-reversed -> linear fp16 store ----
    const float invN = 1.0f / (float)N_FFT;
    for (int k = tid; k < N_FFT; k += T) {
        float2 v = A[slot_of(k)];
        g_Zh[(size_t)b * KDIM + k] = __float2half_rn(v.x * invN);
    }
}

// ---------------------------------------------------------------------------
// fp16 single-term HMMA GEMM:  out = relu(zh @ wh^T + b)
// Tile 128x96, k-chunk 64, grid (32,4)=128 CTAs, 256 thr, 4-stage cp.async.
// ---------------------------------------------------------------------------
#define GTK 64
#define GITERS (KDIM / GTK)          // 250
#define A_PL 16384
#define B_PL 12288
#define STG_BYTES (A_PL + B_PL)      // 28672
#define NST 4
#define GEMM_SMEM (NST * STG_BYTES)  // 114688

static __device__ __forceinline__ void gemm_issue_stage(unsigned sb, int tid, int k0,
                                                        int m0, int n0g) {
    const char* zh = reinterpret_cast<const char*>(g_Zh);
    const char* wh = reinterpret_cast<const char*>(g_Wh);
#pragma unroll
    for (int i = 0; i < 4; ++i) {                 // A: 128 rows x 8 segs
        int lin = i * 256 + tid;
        int r = lin >> 3, seg = lin & 7;
        unsigned d = sb + swz128((unsigned)(r * 128 + seg * 16));
        size_t so = ((size_t)(m0 + r) * KDIM + k0 + seg * 8) * 2;
        CP_ASYNC16(d, zh + so);
    }
#pragma unroll
    for (int i = 0; i < 3; ++i) {                 // B: 96 rows x 8 segs
        int lin = i * 256 + tid;
        int r = lin >> 3, seg = lin & 7;
        unsigned d = sb + A_PL + swz128((unsigned)(r * 128 + seg * 16));
        size_t so = ((size_t)(n0g + r) * KDIM + k0 + seg * 8) * 2;
        CP_ASYNC16(d, wh + so);
    }
}

__global__ __launch_bounds__(256, 1) void gemm_hmma_kernel(const float* __restrict__ bias,
                                                           float* __restrict__ out) {
    extern __shared__ char gsm[];
    const unsigned sbase = smem_u32(gsm);
    const int tid  = threadIdx.x;
    const int lane = tid & 31;
    const int wid  = tid >> 5;
    const int wm   = wid >> 1;          // 0..3 -> 32 m rows each
    const int wn   = wid & 1;           // 0..1 -> 48 n cols each
    const int n0 = blockIdx.x * 96;
    const int m0 = blockIdx.y * 128;

    float acc[2][6][4];
#pragma unroll
    for (int i = 0; i < 2; ++i)
#pragma unroll
        for (int j = 0; j < 6; ++j)
#pragma unroll
            for (int e = 0; e < 4; ++e) acc[i][j][e] = 0.f;

    gemm_issue_stage(sbase, tid, 0, m0, n0);
    CP_COMMIT();
    gemm_issue_stage(sbase + STG_BYTES, tid, GTK, m0, n0);
    CP_COMMIT();
    gemm_issue_stage(sbase + 2 * STG_BYTES, tid, 2 * GTK, m0, n0);
    CP_COMMIT();

    const unsigned aRowSel = (unsigned)(lane & 15) * 128 + ((unsigned)(lane >> 4) << 4);
    const unsigned bRowSel = (unsigned)((lane & 7) | (((lane >> 4) & 1) << 3)) * 128 +
                             (((unsigned)(lane >> 3) & 1) << 4);

    for (int c = 0; c < GITERS; ++c) {
        CP_WAIT2();
        __syncthreads();
        if (c + 3 < GITERS) {
            gemm_issue_stage(sbase + ((c + 3) & 3) * STG_BYTES, tid, (c + 3) * GTK, m0, n0);
        }
        CP_COMMIT();

        const unsigned Ab = sbase + (c & 3) * STG_BYTES;
        const unsigned Bb = Ab + A_PL;
#pragma unroll
        for (int ks = 0; ks < 4; ++ks) {          // 4 sub-chunks of k=16
            unsigned Af[2][4];
            unsigned Bf[3][4];
#pragma unroll
            for (int mf = 0; mf < 2; ++mf) {
                unsigned off = (unsigned)((wm * 32 + mf * 16) * 128 + ks * 32) + aRowSel;
                ldsm_x4(Ab + swz128(off), Af[mf]);
            }
#pragma unroll
            for (int g = 0; g < 3; ++g) {
                unsigned off = (unsigned)((wn * 48 + g * 16) * 128 + ks * 32) + bRowSel;
                ldsm_x4(Bb + swz128(off), Bf[g]);
            }
#pragma unroll
            for (int mf = 0; mf < 2; ++mf)
#pragma unroll
                for (int nf = 0; nf < 6; ++nf)
                    mma_f16(acc[mf][nf], Af[mf], &Bf[nf >> 1][(nf & 1) * 2]);
        }
        __syncthreads();
    }

    // ---- epilogue: bias + relu ----
#pragma unroll
    for (int mf = 0; mf < 2; ++mf) {
        int mlo = m0 + wm * 32 + mf * 16 + (lane >> 2);
#pragma unroll
        for (int nf = 0; nf < 6; ++nf) {
            int n = n0 + wn * 48 + nf * 8 + 2 * (lane & 3);
            if (n < ODIM) {
                float b0 = bias[n], b1 = bias[n + 1];
                float2 v0, v1;
                v0.x = fmaxf(acc[mf][nf][0] + b0, 0.f);
                v0.y = fmaxf(acc[mf][nf][1] + b1, 0.f);
                v1.x = fmaxf(acc[mf][nf][2] + b0, 0.f);
                v1.y = fmaxf(acc[mf][nf][3] + b1, 0.f);
                *reinterpret_cast<float2*>(out + (size_t)mlo * ODIM + n) = v0;
                *reinterpret_cast<float2*>(out + (size_t)(mlo + 8) * ODIM + n) = v1;
            }
        }
    }
}

// ---------------------------------------------------------------------------
extern "C" void kernel_launch(void* const* d_in, const int* in_sizes, int n_in,
                              void* d_out, int out_size) {
    const float* x0  = (const float*)d_in[0];
    const float* x1  = (const float*)d_in[1];
    const float* s1  = (const float*)d_in[2];
    const float* s2  = (const float*)d_in[3];
    const float* Wm  = (const float*)d_in[4];
    const float* bia = (const float*)d_in[5];
    const int*   h1  = (const int*)d_in[6];
    const int*   h2  = (const int*)d_in[7];
    float* out = (float*)d_out;

    // side stream + events for wconv overlap (created on first, uncaptured call)
    static cudaStream_t side = nullptr;
    static cudaEvent_t evFork = nullptr, evJoin = nullptr;
    if (!side) {
        cudaStreamCreateWithFlags(&side, cudaStreamNonBlocking);
        cudaEventCreateWithFlags(&evFork, cudaEventDisableTiming);
        cudaEventCreateWithFlags(&evJoin, cudaEventDisableTiming);
    }

    const int FFT_SMEM = (N_FFT + 128) * (int)sizeof(float2);  // 129 KB
    cudaFuncSetAttribute(fused_fft_kernel, cudaFuncAttributeMaxDynamicSharedMemorySize, FFT_SMEM);
    cudaFuncSetAttribute(gemm_hmma_kernel, cudaFuncAttributeMaxDynamicSharedMemorySize, GEMM_SMEM);

    // fork: wconv on side stream (DRAM-bound; overlaps compute-bound FFT)
    cudaEventRecord(evFork, 0);
    cudaStreamWaitEvent(side, evFork, 0);
    const int wthreads = OPAD * (KDIM / 8);
    wconv_kernel<<<(wthreads + 255) / 256, 256, 0, side>>>(Wm);
    cudaEventRecord(evJoin, side);

    tw_init_kernel<<<(N_FFT + 255) / 256, 256>>>();

    fused_fft_kernel<<<BATCH, 1024, FFT_SMEM>>>(x0, x1, s1, s2, h1, h2);

    // join: gemm needs g_Wh
    cudaStreamWaitEvent(0, evJoin, 0);
    gemm_hmma_kernel<<<dim3((ODIM + 95) / 96, BATCH / 128), 256, GEMM_SMEM>>>(bia, out);
}